// round 11
// baseline (speedup 1.0000x reference)
#include <cuda_runtime.h>
#include <cuda_fp16.h>
#include <math.h>
#include <stdint.h>

#define NSEQ 2048
#define BATCH 2
#define HEADS 8
#define DH 64
#define KRET 32
#define DIM 512
#define NT 32

__device__ float g_q[(size_t)BATCH * HEADS * NSEQ * DH];
__device__ float g_k[(size_t)BATCH * NSEQ * DH];
__device__ float g_v[(size_t)BATCH * NSEQ * DH];
__device__ uint4 g_kf[(size_t)BATCH * NT * 1024];
__device__ uint2 g_vf[(size_t)BATCH * NT * 1024];
__device__ uint32_t g_xf[(size_t)256 * 32 * 32 * 8];
__device__ uint32_t g_af[(size_t)256 * 32 * 32 * 8];
__device__ uint32_t g_wqf[(size_t)64 * 32 * 32 * 4];
__device__ uint32_t g_wkvf[(size_t)16 * 32 * 32 * 4];
__device__ uint32_t g_woutf[(size_t)64 * 32 * 32 * 4];

__device__ __forceinline__ void mma16(float* d, uint32_t a0, uint32_t a1, uint32_t a2,
                                      uint32_t a3, uint32_t b0, uint32_t b1) {
    asm volatile("mma.sync.aligned.m16n8k16.row.col.f32.f16.f16.f32 "
        "{%0,%1,%2,%3}, {%4,%5,%6,%7}, {%8,%9}, {%0,%1,%2,%3};"
        : "+f"(d[0]), "+f"(d[1]), "+f"(d[2]), "+f"(d[3])
        : "r"(a0), "r"(a1), "r"(a2), "r"(a3), "r"(b0), "r"(b1));
}
__device__ __forceinline__ uint32_t h2bits(__half2 h) {
    uint32_t u; *(__half2*)&u = h; return u;
}
__device__ __forceinline__ uint32_t split_pair_h(float a, float b, uint32_t& lo) {
    __half ha = __float2half_rn(a), hb = __float2half_rn(b);
    float ra = a - __half2float(ha), rb = b - __half2float(hb);
    lo = h2bits(__floats2half2_rn(ra, rb));
    return h2bits(__halves2half2(ha, hb));
}
__device__ __forceinline__ uint32_t s2u(const void* p) {
    return (uint32_t)__cvta_generic_to_shared(p);
}
__device__ __forceinline__ void cpa16(uint32_t s, const void* g) {
    asm volatile("cp.async.cg.shared.global [%0], [%1], 16;" :: "r"(s), "l"(g) : "memory");
}

// ---------------------------------------------------------------------------
__global__ __launch_bounds__(256) void pack_x(const float* __restrict__ x)
{
    int s = blockIdx.x * 256 + threadIdx.x;
    int band = s >> 10, rem = s & 1023;
    int kfg = rem >> 5, ln = rem & 31;
    int gid = ln >> 2, tig = ln & 3;
    const float* base = x + (size_t)(band * 16 + gid) * DIM + kfg * 16 + 2 * tig;
    float2 x00 = *(const float2*)base;
    float2 x10 = *(const float2*)(base + 8 * DIM);
    float2 x01 = *(const float2*)(base + 8);
    float2 x11 = *(const float2*)(base + 8 * DIM + 8);
    uint32_t l0, l1, l2, l3;
    uint32_t h0 = split_pair_h(x00.x, x00.y, l0);
    uint32_t h1 = split_pair_h(x10.x, x10.y, l1);
    uint32_t h2 = split_pair_h(x01.x, x01.y, l2);
    uint32_t h3 = split_pair_h(x11.x, x11.y, l3);
    *(uint4*)&g_xf[(size_t)s * 8]     = make_uint4(h0, h1, h2, h3);
    *(uint4*)&g_xf[(size_t)s * 8 + 4] = make_uint4(l0, l1, l2, l3);
}

// ---------------------------------------------------------------------------
__global__ __launch_bounds__(256) void pack_w(const float* __restrict__ Wq,
                                              const float* __restrict__ Wkv,
                                              const float* __restrict__ Wout)
{
    int sel = blockIdx.y;
    const float* W = sel == 0 ? Wq : (sel == 1 ? Wkv : Wout);
    uint32_t* out  = sel == 0 ? g_wqf : (sel == 1 ? g_wkvf : g_woutf);
    int N = (sel == 1) ? 128 : 512;
    int s = blockIdx.x * 256 + threadIdx.x;
    if (s >= (N / 8) * 1024) return;
    int nfg = s >> 10, rem = s & 1023;
    int kfg = rem >> 5, ln = rem & 31;
    int gid = ln >> 2, tig = ln & 3;
    int n = nfg * 8 + gid, k0 = kfg * 16 + 2 * tig;
    uint32_t bl0, bl1;
    uint32_t bh0 = split_pair_h(W[(size_t)k0 * N + n], W[(size_t)(k0 + 1) * N + n], bl0);
    uint32_t bh1 = split_pair_h(W[(size_t)(k0 + 8) * N + n], W[(size_t)(k0 + 9) * N + n], bl1);
    *(uint4*)&out[(size_t)s * 4] = make_uint4(bh0, bh1, bl0, bl1);
}

// ---------------------------------------------------------------------------
// Shared GEMM mainloop: returns accumulators for a 64x64 tile.
// ---------------------------------------------------------------------------
struct GemmCtx {
    float S[4][4];
    int row0, colw;
};
__device__ __forceinline__ void gemm_core(const uint32_t* APK, const uint32_t* BPK,
                                          int band0, int nf0, int KFG,
                                          uint32_t* AF, uint32_t* BF, GemmCtx& cx)
{
    const int tid = threadIdx.x, lane = tid & 31, w = tid >> 5;
    const int mw = w & 3, nh = w >> 2;
    const int nslab = KFG >> 1;
    const uint32_t a_su[2] = {s2u(AF), s2u(AF + 2048)};
    const uint32_t b_su[2] = {s2u(BF), s2u(BF + 2048)};

    #pragma unroll
    for (int r = 0; r < 4; r++)
        #pragma unroll
        for (int c = 0; c < 4; c++) cx.S[r][c] = 0.f;

    #pragma unroll
    for (int it = 0; it < 2; it++) {
        int idx = tid + it * 256;
        int kf2 = idx >> 8, mb = (idx >> 6) & 3, ln = (idx >> 1) & 31, hf = idx & 1;
        cpa16(a_su[0] + (((kf2 * 4 + mb) * 32 + ln) * 8 + hf * 4) * 4,
              APK + ((size_t)((band0 + mb) * KFG + kf2) * 32 + ln) * 8 + hf * 4);
        int nf = (idx >> 5) & 7, lnb = idx & 31;
        cpa16(b_su[0] + ((kf2 * 8 + nf) * 32 + lnb) * 16,
              BPK + ((size_t)((nf0 + nf) * KFG + kf2) * 32 + lnb) * 4);
    }
    asm volatile("cp.async.commit_group;" ::: "memory");

    for (int ks = 0; ks < nslab; ks++) {
        const int cur = ks & 1;
        __syncthreads();
        if (ks + 1 < nslab) {
            const int st = cur ^ 1;
            #pragma unroll
            for (int it = 0; it < 2; it++) {
                int idx = tid + it * 256;
                int kf2 = idx >> 8, mb = (idx >> 6) & 3, ln = (idx >> 1) & 31, hf = idx & 1;
                int kfg = (ks + 1) * 2 + kf2;
                cpa16(a_su[st] + (((kf2 * 4 + mb) * 32 + ln) * 8 + hf * 4) * 4,
                      APK + ((size_t)((band0 + mb) * KFG + kfg) * 32 + ln) * 8 + hf * 4);
                int nf = (idx >> 5) & 7, lnb = idx & 31;
                cpa16(b_su[st] + ((kf2 * 8 + nf) * 32 + lnb) * 16,
                      BPK + ((size_t)((nf0 + nf) * KFG + kfg) * 32 + lnb) * 4);
            }
        }
        asm volatile("cp.async.commit_group;" ::: "memory");
        asm volatile("cp.async.wait_group 1;" ::: "memory");
        __syncthreads();

        uint32_t* AFc = AF + cur * 2048;
        uint32_t* BFc = BF + cur * 2048;
        #pragma unroll
        for (int kf2 = 0; kf2 < 2; kf2++) {
            const uint32_t* ap = &AFc[((kf2 * 4 + mw) * 32 + lane) * 8];
            uint4 ah = *(const uint4*)ap;
            uint4 al = *(const uint4*)(ap + 4);
            #pragma unroll
            for (int nf = 0; nf < 4; nf++) {
                uint4 kb = *(const uint4*)&BFc[((kf2 * 8 + nh * 4 + nf) * 32 + lane) * 4];
                mma16(cx.S[nf], ah.x, ah.y, ah.z, ah.w, kb.x, kb.y);
                mma16(cx.S[nf], al.x, al.y, al.z, al.w, kb.x, kb.y);
                mma16(cx.S[nf], ah.x, ah.y, ah.z, ah.w, kb.z, kb.w);
            }
        }
    }
    cx.colw = nh * 32;
}

// norm helper: cross-half row sumsq
__device__ __forceinline__ float row_ss(const GemmCtx& cx, int rr, float* ssbuf)
{
    const int tid = threadIdx.x, lane = tid & 31, w = tid >> 5;
    const int mw = w & 3, nh = w >> 2;
    const int gid = lane >> 2, tig = lane & 3;
    float ss = 0.f;
    #pragma unroll
    for (int nf = 0; nf < 4; nf++)
        ss += cx.S[nf][2 * rr] * cx.S[nf][2 * rr] + cx.S[nf][2 * rr + 1] * cx.S[nf][2 * rr + 1];
    ss += __shfl_xor_sync(0xffffffffu, ss, 1);
    ss += __shfl_xor_sync(0xffffffffu, ss, 2);
    if (tig == 0) ssbuf[nh * 64 + mw * 16 + gid + rr * 8] = ss;
    return ss;
}

// ---------------------------------------------------------------------------
// Fused Wq+Wkv GEMM: grid (10, 64). x<8 -> Wq (Q-norm epilogue); x>=8 -> Wkv.
// ---------------------------------------------------------------------------
__global__ __launch_bounds__(256) void gemm_qkv()
{
    __shared__ uint32_t AF[2 * 2048];
    __shared__ uint32_t BF[2 * 2048];
    __shared__ float ssbuf[128];

    const int tid = threadIdx.x, lane = tid & 31, w = tid >> 5;
    const int mw = w & 3;
    const int gid = lane >> 2, tig = lane & 3;
    const int r0 = blockIdx.y * 64;
    const bool is_q = blockIdx.x < 8;
    const int xk = is_q ? blockIdx.x : blockIdx.x - 8;

    GemmCtx cx;
    gemm_core(g_xf, is_q ? g_wqf : g_wkvf, r0 >> 4, xk * 8, DIM >> 4, AF, BF, cx);
    cx.row0 = r0 + mw * 16 + gid;

    bool needs_norm = is_q || (xk == 0);
    if (needs_norm) {
        row_ss(cx, 0, ssbuf);
        row_ss(cx, 1, ssbuf);
    }
    __syncthreads();

    #pragma unroll
    for (int rr = 0; rr < 2; rr++) {
        int rloc = mw * 16 + gid + rr * 8;
        int row = r0 + rloc;
        if (is_q) {
            float ss = ssbuf[rloc] + ssbuf[64 + rloc];
            float inv = 1.0f / fmaxf(sqrtf(ss), 1e-12f);
            int bb = row >> 11, t = row & 2047;
            size_t base = (((size_t)bb * HEADS + xk) * NSEQ + t) * DH;
            #pragma unroll
            for (int nf = 0; nf < 4; nf++) {
                float2 v = make_float2(cx.S[nf][2 * rr] * inv, cx.S[nf][2 * rr + 1] * inv);
                *(float2*)&g_q[base + cx.colw + nf * 8 + 2 * tig] = v;
            }
        } else {
            size_t base = (size_t)row * DH;
            if (xk == 0) {
                float ss = ssbuf[rloc] + ssbuf[64 + rloc];
                float inv = 1.0f / fmaxf(sqrtf(ss), 1e-12f);
                #pragma unroll
                for (int nf = 0; nf < 4; nf++) {
                    float2 v = make_float2(cx.S[nf][2 * rr] * inv, cx.S[nf][2 * rr + 1] * inv);
                    *(float2*)&g_k[base + cx.colw + nf * 8 + 2 * tig] = v;
                }
            } else {
                #pragma unroll
                for (int nf = 0; nf < 4; nf++) {
                    float2 v = make_float2(cx.S[nf][2 * rr], cx.S[nf][2 * rr + 1]);
                    *(float2*)&g_v[base + cx.colw + nf * 8 + 2 * tig] = v;
                }
            }
        }
    }
}

// ---------------------------------------------------------------------------
// Output GEMM (mode 0 only): C = g_af @ g_woutf.
// ---------------------------------------------------------------------------
__global__ __launch_bounds__(256) void gemm_out(float* __restrict__ C)
{
    __shared__ uint32_t AF[2 * 2048];
    __shared__ uint32_t BF[2 * 2048];

    const int tid = threadIdx.x, lane = tid & 31, w = tid >> 5;
    const int mw = w & 3;
    const int gid = lane >> 2, tig = lane & 3;
    const int r0 = blockIdx.y * 64, c0 = blockIdx.x * 64;

    GemmCtx cx;
    gemm_core(g_af, g_woutf, r0 >> 4, c0 >> 3, DIM >> 4, AF, BF, cx);
    const int row0 = r0 + mw * 16 + gid;

    #pragma unroll
    for (int rr = 0; rr < 2; rr++)
        #pragma unroll
        for (int nf = 0; nf < 4; nf++) {
            float2 v = make_float2(cx.S[nf][2 * rr], cx.S[nf][2 * rr + 1]);
            *(float2*)&C[(size_t)(row0 + rr * 8) * DIM + c0 + cx.colw + nf * 8 + 2 * tig] = v;
        }
}

// ---------------------------------------------------------------------------
__global__ __launch_bounds__(128) void pack_kv()
{
    const int kt = blockIdx.x, bb = blockIdx.y, tid = threadIdx.x;
    const size_t r0 = (size_t)bb * NSEQ + (size_t)kt * 64;
    const size_t obase = ((size_t)bb * NT + kt) * 1024;

    #pragma unroll
    for (int it = 0; it < 8; it++) {
        int s = tid + it * 128;
        int nf = s >> 7, kf = (s >> 5) & 3, lane = s & 31;
        int gid = lane >> 2, tig = lane & 3;
        size_t key = r0 + nf * 8 + gid;
        int d0 = kf * 16 + 2 * tig;
        float2 k0 = *(const float2*)&g_k[key * DH + d0];
        float2 k1 = *(const float2*)&g_k[key * DH + d0 + 8];
        uint32_t bl0, bl1;
        uint32_t bh0 = split_pair_h(k0.x, k0.y, bl0);
        uint32_t bh1 = split_pair_h(k1.x, k1.y, bl1);
        g_kf[obase + s] = make_uint4(bh0, bh1, bl0, bl1);
    }
    #pragma unroll
    for (int it = 0; it < 8; it++) {
        int s = tid + it * 128;
        int kg = s >> 8, nfd = (s >> 5) & 7, lane = s & 31;
        int gid = lane >> 2, tig = lane & 3;
        size_t key0 = r0 + kg * 16 + 2 * tig;
        int d = nfd * 8 + gid;
        uint32_t b0 = h2bits(__floats2half2_rn(g_v[key0 * DH + d], g_v[(key0 + 1) * DH + d]));
        uint32_t b1 = h2bits(__floats2half2_rn(g_v[(key0 + 8) * DH + d], g_v[(key0 + 9) * DH + d]));
        g_vf[obase + s] = make_uint2(b0, b1);
    }
}

// ---------------------------------------------------------------------------
// Flash attention: each block processes TWO query tiles (qtA=31-z heavy,
// qtB=z light) -> all 256 blocks have identical work (33 tile-visits).
// Group-private staging + named barriers (R10 structure).
// ---------------------------------------------------------------------------
#define STB 10752
__global__ __launch_bounds__(256, 2) void attn_mma(const float* __restrict__ memkv,
                                                   const float* __restrict__ rel,
                                                   const float* __restrict__ scale_param)
{
    extern __shared__ uint32_t smu[];
    uint32_t* QF  = smu;                              // 4096
    float* PMEM = (float*)(smu + 4096 + STB);         // aliases stage1
    float* OSM  = (float*)(smu + 4096 + STB + 2304);  // aliases stage1
    float* OMG  = (float*)(smu + 4096);               // aliases stage0
    float* RM   = (float*)(smu + 25600);              // 128
    float* RL   = RM + 128;                           // 128

    const int bb = blockIdx.x, hh = blockIdx.y;
    const int tid = threadIdx.x, lane = tid & 31, w = tid >> 5;
    const int mw = w & 3, ng = w >> 2;
    const int g = ng, gtid = tid & 127;
    const int gid = lane >> 2, tig = lane & 3;
    const int il0 = 16 * mw + gid;
    const float scale = expf(scale_param[hh]);

    const uint32_t ks_su[2] = {s2u(smu + 4096  + g * 2048),
                               s2u(smu + 4096  + g * 2048 + STB)};
    const uint32_t vs_su[2] = {s2u(smu + 8192  + g * 1024),
                               s2u(smu + 8192  + g * 1024 + STB)};
    const uint32_t bs_su[2] = {s2u(smu + 10240 + g * 2304),
                               s2u(smu + 10240 + g * 2304 + STB)};
    const uint4* ktileb = g_kf + (size_t)bb * NT * 1024 + g * 512;
    const uint4* vtileb = (const uint4*)(g_vf + (size_t)bb * NT * 1024 + g * 512);

    for (int half = 0; half < 2; half++) {
        const int qt = half ? (int)blockIdx.z : (NT - 1 - (int)blockIdx.z);
        if (half) __syncthreads();   // half-A OMG/QF consumers done before reuse

        const float* relrow = rel + ((size_t)hh * NSEQ + (size_t)qt * 64) * NSEQ;

        // ---- prefetch tile 0 into stage 0 (group-private) ----
        {
            #pragma unroll
            for (int it = 0; it < 4; it++)
                cpa16(ks_su[0] + (gtid + it * 128) * 16, ktileb + gtid + it * 128);
            #pragma unroll
            for (int it = 0; it < 2; it++)
                cpa16(vs_su[0] + (gtid + it * 128) * 16, vtileb + gtid + it * 128);
            const float* bsrc = relrow + g * 32;
            #pragma unroll
            for (int it = 0; it < 4; it++) {
                int c = gtid + it * 128;
                int r = c >> 3, c4 = c & 7;
                cpa16(bs_su[0] + (r * 36 + c4 * 4) * 4, bsrc + (size_t)r * NSEQ + c4 * 4);
            }
            asm volatile("cp.async.commit_group;" ::: "memory");
        }

        // ---- Q fragments (built by ng==0 warps) ----
        const float* qbase = g_q + (((size_t)bb * HEADS + hh) * NSEQ + (size_t)qt * 64) * DH;
        if (ng == 0) {
            #pragma unroll
            for (int kf = 0; kf < 4; kf++) {
                int d0 = kf * 16 + 2 * tig;
                float2 q00 = *(const float2*)&qbase[il0 * DH + d0];
                float2 q10 = *(const float2*)&qbase[(il0 + 8) * DH + d0];
                float2 q01 = *(const float2*)&qbase[il0 * DH + d0 + 8];
                float2 q11 = *(const float2*)&qbase[(il0 + 8) * DH + d0 + 8];
                uint32_t al0, al1, al2, al3;
                uint32_t ah0 = split_pair_h(q00.x, q00.y, al0);
                uint32_t ah1 = split_pair_h(q10.x, q10.y, al1);
                uint32_t ah2 = split_pair_h(q01.x, q01.y, al2);
                uint32_t ah3 = split_pair_h(q11.x, q11.y, al3);
                uint32_t* qp = &QF[((mw * 4 + kf) * 32 + lane) * 8];
                *(uint4*)qp       = make_uint4(ah0, ah1, ah2, ah3);
                *(uint4*)(qp + 4) = make_uint4(al0, al1, al2, al3);
            }
        }

        // ---- memory-attention prologue (SIMT fp32), 4 threads per query ----
        {
            int qi = tid >> 2, qtr = tid & 3;
            size_t gi = (size_t)qt * 64 + qi;
            const float* qrow = qbase + qi * DH + qtr * 16;
            float4 q4[4];
            #pragma unroll
            for (int u = 0; u < 4; u++) q4[u] = *(const float4*)&qrow[u * 4];
            const float* mk = memkv + ((((size_t)bb * HEADS + hh) * NSEQ + gi) * KRET) * 128
                            + qtr * 16;
            float sj[8];
            for (int j = 0; j < 32; j++) {
                const float* kp = mk + (size_t)j * 128;
                float p = 0.f;
                #pragma unroll
                for (int u = 0; u < 4; u++) {
                    float4 k4 = *(const float4*)&kp[u * 4];
                    p += q4[u].x * k4.x + q4[u].y * k4.y + q4[u].z * k4.z + q4[u].w * k4.w;
                }
                p += __shfl_xor_sync(0xffffffffu, p, 1);
                p += __shfl_xor_sync(0xffffffffu, p, 2);
                if ((j & 3) == qtr) sj[j >> 2] = p * scale;
            }
            float mx = -3.0e38f;
            #pragma unroll
            for (int u = 0; u < 8; u++) mx = fmaxf(mx, sj[u]);
            mx = fmaxf(mx, __shfl_xor_sync(0xffffffffu, mx, 1));
            mx = fmaxf(mx, __shfl_xor_sync(0xffffffffu, mx, 2));
            float ls = 0.f;
            #pragma unroll
            for (int u = 0; u < 8; u++) {
                float pe = __expf(sj[u] - mx);
                ls += pe;
                PMEM[qi * 36 + u * 4 + qtr] = pe;
            }
            ls += __shfl_xor_sync(0xffffffffu, ls, 1);
            ls += __shfl_xor_sync(0xffffffffu, ls, 2);
            if (!qtr) { RM[qi] = mx; RL[qi] = ls; }
        }
        __syncthreads();

        {
            int qi = tid >> 2, qtr = tid & 3;
            size_t gi = (size_t)qt * 64 + qi;
            const float* vb = memkv + ((((size_t)bb * HEADS + hh) * NSEQ + gi) * KRET) * 128
                            + 64 + qtr * 16;
            float4 acc[4] = {};
            for (int j = 0; j < 32; j++) {
                float p = PMEM[qi * 36 + j];
                #pragma unroll
                for (int u = 0; u < 4; u++) {
                    float4 v4 = *(const float4*)&vb[(size_t)j * 128 + u * 4];
                    acc[u].x += p * v4.x; acc[u].y += p * v4.y;
                    acc[u].z += p * v4.z; acc[u].w += p * v4.w;
                }
            }
            #pragma unroll
            for (int u = 0; u < 4; u++)
                *(float4*)&OSM[qi * 68 + qtr * 16 + u * 4] = acc[u];
        }
        __syncthreads();

        // ---- seed accumulators ----
        float O[8][4] = {}, m_r[2], l_r[2];
        if (ng == 0) {
            m_r[0] = RM[il0];     l_r[0] = RL[il0];
            m_r[1] = RM[il0 + 8]; l_r[1] = RL[il0 + 8];
            #pragma unroll
            for (int nf = 0; nf < 8; nf++) {
                O[nf][0] = OSM[il0 * 68 + nf * 8 + 2 * tig];
                O[nf][1] = OSM[il0 * 68 + nf * 8 + 2 * tig + 1];
                O[nf][2] = OSM[(il0 + 8) * 68 + nf * 8 + 2 * tig];
                O[nf][3] = OSM[(il0 + 8) * 68 + nf * 8 + 2 * tig + 1];
            }
        } else {
            m_r[0] = m_r[1] = -3.0e38f;
            l_r[0] = l_r[1] = 0.f;
        }
        __syncthreads();   // OSM/PMEM reads done before stage-1 prefetch overwrites

        // ---- causal local tiles: group-scoped pipeline ----
        for (int kt = 0; kt <= qt; kt++) {
            const int cur = kt & 1;
            asm volatile("bar.sync %0, 128;" :: "r"(1 + g) : "memory");
            if (kt + 1 <= qt) {
                const int st = cur ^ 1;
                const uint4* ks = ktileb + (size_t)(kt + 1) * 1024;
                #pragma unroll
                for (int it = 0; it < 4; it++)
                    cpa16(ks_su[st] + (gtid + it * 128) * 16, ks + gtid + it * 128);
                const uint4* vs = vtileb + (size_t)(kt + 1) * 512;
                #pragma unroll
                for (int it = 0; it < 2; it++)
                    cpa16(vs_su[st] + (gtid + it * 128) * 16, vs + gtid + it * 128);
                const float* bsrc = relrow + (size_t)(kt + 1) * 64 + g * 32;
                #pragma unroll
                for (int it = 0; it < 4; it++) {
                    int c = gtid + it * 128;
                    int r = c >> 3, c4 = c & 7;
                    cpa16(bs_su[st] + (r * 36 + c4 * 4) * 4, bsrc + (size_t)r * NSEQ + c4 * 4);
                }
            }
            asm volatile("cp.async.commit_group;" ::: "memory");
            asm volatile("cp.async.wait_group 1;" ::: "memory");
            asm volatile("bar.sync %0, 128;" :: "r"(1 + g) : "memory");

            const uint32_t* KSc = smu + 4096  + g * 2048 + cur * STB;
            const uint32_t* VSc = smu + 8192  + g * 1024 + cur * STB;
            const float*    BSc = (const float*)(smu + 10240 + g * 2304 + cur * STB);

            float S[4][4] = {};
            #pragma unroll
            for (int kf = 0; kf < 4; kf++) {
                const uint32_t* qp = &QF[((mw * 4 + kf) * 32 + lane) * 8];
                uint4 ah = *(const uint4*)qp;
                uint4 al = *(const uint4*)(qp + 4);
                #pragma unroll
                for (int nf = 0; nf < 4; nf++) {
                    uint4 kb = *(const uint4*)&KSc[((nf * 4 + kf) * 32 + lane) * 4];
                    mma16(S[nf], ah.x, ah.y, ah.z, ah.w, kb.x, kb.y);
                    mma16(S[nf], al.x, al.y, al.z, al.w, kb.x, kb.y);
                    mma16(S[nf], ah.x, ah.y, ah.z, ah.w, kb.z, kb.w);
                }
            }

            uint32_t ph[4][2];
            #pragma unroll
            for (int rr = 0; rr < 2; rr++) {
                int il = il0 + rr * 8;
                float mx = -3.0e38f;
                #pragma unroll
                for (int nf = 0; nf < 4; nf++) {
                    int colb = g * 32 + nf * 8 + 2 * tig;
                    float2 b2 = *(const float2*)&BSc[il * 36 + nf * 8 + 2 * tig];
                    float s0 = fmaf(S[nf][2 * rr], scale, b2.x);
                    float s1 = fmaf(S[nf][2 * rr + 1], scale, b2.y);
                    if (kt == qt) {
                        if (colb     > il) s0 = -3.0e38f;
                        if (colb + 1 > il) s1 = -3.0e38f;
                    }
                    S[nf][2 * rr] = s0; S[nf][2 * rr + 1] = s1;
                    mx = fmaxf(mx, fmaxf(s0, s1));
                }
                mx = fmaxf(mx, __shfl_xor_sync(0xffffffffu, mx, 1));
                mx = fmaxf(mx, __shfl_xor_sync(0xffffffffu, mx, 2));
                float mnew = fmaxf(m_r[rr], mx);
                float f = __expf(m_r[rr] - mnew);
                m_r[rr] = mnew;
                float ls = 0.f;
                #pragma unroll
                for (int nf = 0; nf < 4; nf++) {
                    float p0 = __expf(S[nf][2 * rr] - mnew);
                    float p1 = __expf(S[nf][2 * rr + 1] - mnew);
                    ls += p0 + p1;
                    ph[nf][rr] = h2bits(__floats2half2_rn(p0, p1));
                }
                #pragma unroll
                for (int nf = 0; nf < 8; nf++) {
                    O[nf][2 * rr]     *= f;
                    O[nf][2 * rr + 1] *= f;
                }
                ls += __shfl_xor_sync(0xffffffffu, ls, 1);
                ls += __shfl_xor_sync(0xffffffffu, ls, 2);
                l_r[rr] = l_r[rr] * f + ls;
            }

            #pragma unroll
            for (int kfl = 0; kfl < 2; kfl++) {
                uint32_t a0 = ph[2 * kfl][0], a1 = ph[2 * kfl][1];
                uint32_t a2 = ph[2 * kfl + 1][0], a3 = ph[2 * kfl + 1][1];
                #pragma unroll
                for (int nfd = 0; nfd < 8; nfd++) {
                    uint2 vb = *(const uint2*)&VSc[((kfl * 8 + nfd) * 32 + lane) * 2];
                    mma16(O[nfd], a0, a1, a2, a3, vb.x, vb.y);
                }
            }
        }

        // ---- 2-way merge across ng and emit gemm3 A-fragments ----
        asm volatile("cp.async.wait_group 0;" ::: "memory");
        __syncthreads();
        if (ng == 1) {
            #pragma unroll
            for (int rr = 0; rr < 2; rr++) {
                int il = il0 + rr * 8;
                RM[64 + il] = m_r[rr];
                RL[64 + il] = l_r[rr];
                #pragma unroll
                for (int nf = 0; nf < 8; nf++) {
                    float2 v = make_float2(O[nf][2 * rr], O[nf][2 * rr + 1]);
                    *(float2*)&OMG[il * 72 + nf * 8 + 2 * tig] = v;
                }
            }
        }
        __syncthreads();
        if (ng == 0) {
            #pragma unroll
            for (int rr = 0; rr < 2; rr++) {
                int il = il0 + rr * 8;
                float m1 = RM[64 + il], l1 = RL[64 + il];
                float m = fmaxf(m_r[rr], m1);
                float f0 = __expf(m_r[rr] - m), f1 = __expf(m1 - m);
                float inv = 1.0f / (l_r[rr] * f0 + l1 * f1);
                #pragma unroll
                for (int nf = 0; nf < 8; nf++) {
                    float2 o1 = *(const float2*)&OMG[il * 72 + nf * 8 + 2 * tig];
                    O[nf][2 * rr]     = (O[nf][2 * rr]     * f0 + o1.x * f1) * inv;
                    O[nf][2 * rr + 1] = (O[nf][2 * rr + 1] * f0 + o1.y * f1) * inv;
                }
            }
            int band = bb * 128 + qt * 4 + mw;
            #pragma unroll
            for (int kf = 0; kf < 4; kf++) {
                uint32_t l0, l1, l2, l3;
                uint32_t h0 = split_pair_h(O[2 * kf][0],     O[2 * kf][1],     l0);
                uint32_t h1 = split_pair_h(O[2 * kf][2],     O[2 * kf][3],     l1);
                uint32_t h2 = split_pair_h(O[2 * kf + 1][0], O[2 * kf + 1][1], l2);
                uint32_t h3 = split_pair_h(O[2 * kf + 1][2], O[2 * kf + 1][3], l3);
                size_t slot = ((size_t)band * 32 + (hh * 4 + kf)) * 32 + lane;
                *(uint4*)&g_af[slot * 8]     = make_uint4(h0, h1, h2, h3);
                *(uint4*)&g_af[slot * 8 + 4] = make_uint4(l0, l1, l2, l3);
            }
        }
    }
}

// ---------------------------------------------------------------------------
extern "C" void kernel_launch(void* const* d_in, const int* in_sizes, int n_in,
                              void* d_out, int out_size)
{
    const float* x      = (const float*)d_in[0];
    const float* memkv  = (const float*)d_in[1];
    const float* rel    = (const float*)d_in[3];
    const float* Wq     = (const float*)d_in[4];
    const float* Wkv    = (const float*)d_in[5];
    const float* Wout   = (const float*)d_in[6];
    const float* scalep = (const float*)d_in[7];
    float* out = (float*)d_out;

    const int SMEM = 25856 * (int)sizeof(uint32_t);   // 103424 B
    cudaFuncSetAttribute(attn_mma, cudaFuncAttributeMaxDynamicSharedMemorySize, SMEM);

    const int M = BATCH * NSEQ;
    pack_x<<<1024, 256>>>(x);
    pack_w<<<dim3(256, 3), 256>>>(Wq, Wkv, Wout);
    gemm_qkv<<<dim3(10, M / 64), 256>>>();
    pack_kv<<<dim3(NT, BATCH), 128>>>();
    attn_mma<<<dim3(BATCH, HEADS, NT / 2), 256, SMEM>>>(memkv, rel, scalep);
    gemm_out<<<dim3(DIM / 64, M / 64), 256>>>(out);
}

// round 12
// speedup vs baseline: 1.0788x; 1.0788x over previous
#include <cuda_runtime.h>
#include <cuda_fp16.h>
#include <math.h>
#include <stdint.h>

#define NSEQ 2048
#define BATCH 2
#define HEADS 8
#define DH 64
#define KRET 32
#define DIM 512
#define NT 32
#define L2E 1.4426950408889634f

__device__ float g_q[(size_t)BATCH * HEADS * NSEQ * DH];
__device__ uint4 g_kf[(size_t)BATCH * NT * 1024];
__device__ uint2 g_vf[(size_t)BATCH * NT * 1024];
__device__ uint32_t g_xf[(size_t)256 * 32 * 32 * 8];
__device__ uint32_t g_af[(size_t)256 * 32 * 32 * 8];
__device__ uint32_t g_wqf[(size_t)64 * 32 * 32 * 4];
__device__ uint32_t g_wkvf[(size_t)16 * 32 * 32 * 4];
__device__ uint32_t g_woutf[(size_t)64 * 32 * 32 * 4];

__device__ __forceinline__ void mma16(float* d, uint32_t a0, uint32_t a1, uint32_t a2,
                                      uint32_t a3, uint32_t b0, uint32_t b1) {
    asm volatile("mma.sync.aligned.m16n8k16.row.col.f32.f16.f16.f32 "
        "{%0,%1,%2,%3}, {%4,%5,%6,%7}, {%8,%9}, {%0,%1,%2,%3};"
        : "+f"(d[0]), "+f"(d[1]), "+f"(d[2]), "+f"(d[3])
        : "r"(a0), "r"(a1), "r"(a2), "r"(a3), "r"(b0), "r"(b1));
}
__device__ __forceinline__ float ex2(float x) {
    float r; asm("ex2.approx.f32 %0, %1;" : "=f"(r) : "f"(x)); return r;
}
__device__ __forceinline__ uint32_t h2bits(__half2 h) {
    uint32_t u; *(__half2*)&u = h; return u;
}
__device__ __forceinline__ uint32_t split_pair_h(float a, float b, uint32_t& lo) {
    __half ha = __float2half_rn(a), hb = __float2half_rn(b);
    float ra = a - __half2float(ha), rb = b - __half2float(hb);
    lo = h2bits(__floats2half2_rn(ra, rb));
    return h2bits(__halves2half2(ha, hb));
}
__device__ __forceinline__ uint32_t s2u(const void* p) {
    return (uint32_t)__cvta_generic_to_shared(p);
}
__device__ __forceinline__ void cpa16(uint32_t s, const void* g) {
    asm volatile("cp.async.cg.shared.global [%0], [%1], 16;" :: "r"(s), "l"(g) : "memory");
}

// ---------------------------------------------------------------------------
// Merged input pack: blocks [0,1024) pack x; [1024,1792) pack W.
// ---------------------------------------------------------------------------
__global__ __launch_bounds__(256) void pack_in(const float* __restrict__ x,
                                               const float* __restrict__ Wq,
                                               const float* __restrict__ Wkv,
                                               const float* __restrict__ Wout)
{
    int bx = blockIdx.x;
    if (bx < 1024) {
        int s = bx * 256 + threadIdx.x;
        int band = s >> 10, rem = s & 1023;
        int kfg = rem >> 5, ln = rem & 31;
        int gid = ln >> 2, tig = ln & 3;
        const float* base = x + (size_t)(band * 16 + gid) * DIM + kfg * 16 + 2 * tig;
        float2 x00 = *(const float2*)base;
        float2 x10 = *(const float2*)(base + 8 * DIM);
        float2 x01 = *(const float2*)(base + 8);
        float2 x11 = *(const float2*)(base + 8 * DIM + 8);
        uint32_t l0, l1, l2, l3;
        uint32_t h0 = split_pair_h(x00.x, x00.y, l0);
        uint32_t h1 = split_pair_h(x10.x, x10.y, l1);
        uint32_t h2 = split_pair_h(x01.x, x01.y, l2);
        uint32_t h3 = split_pair_h(x11.x, x11.y, l3);
        *(uint4*)&g_xf[(size_t)s * 8]     = make_uint4(h0, h1, h2, h3);
        *(uint4*)&g_xf[(size_t)s * 8 + 4] = make_uint4(l0, l1, l2, l3);
    } else {
        int sel = (bx - 1024) >> 8;
        const float* W = sel == 0 ? Wq : (sel == 1 ? Wkv : Wout);
        uint32_t* out  = sel == 0 ? g_wqf : (sel == 1 ? g_wkvf : g_woutf);
        int N = (sel == 1) ? 128 : 512;
        int s = ((bx - 1024) & 255) * 256 + threadIdx.x;
        if (s >= (N / 8) * 1024) return;
        int nfg = s >> 10, rem = s & 1023;
        int kfg = rem >> 5, ln = rem & 31;
        int gid = ln >> 2, tig = ln & 3;
        int n = nfg * 8 + gid, k0 = kfg * 16 + 2 * tig;
        uint32_t bl0, bl1;
        uint32_t bh0 = split_pair_h(W[(size_t)k0 * N + n], W[(size_t)(k0 + 1) * N + n], bl0);
        uint32_t bh1 = split_pair_h(W[(size_t)(k0 + 8) * N + n], W[(size_t)(k0 + 9) * N + n], bl1);
        *(uint4*)&out[(size_t)s * 4] = make_uint4(bh0, bh1, bl0, bl1);
    }
}

// ---------------------------------------------------------------------------
// Shared GEMM mainloop.
// ---------------------------------------------------------------------------
struct GemmCtx { float S[4][4]; int colw; };
__device__ __forceinline__ void gemm_core(const uint32_t* APK, const uint32_t* BPK,
                                          int band0, int nf0, int KFG,
                                          uint32_t* AF, uint32_t* BF, GemmCtx& cx)
{
    const int tid = threadIdx.x, lane = tid & 31, w = tid >> 5;
    const int mw = w & 3, nh = w >> 2;
    const int nslab = KFG >> 1;
    const uint32_t a_su[2] = {s2u(AF), s2u(AF + 2048)};
    const uint32_t b_su[2] = {s2u(BF), s2u(BF + 2048)};

    #pragma unroll
    for (int r = 0; r < 4; r++)
        #pragma unroll
        for (int c = 0; c < 4; c++) cx.S[r][c] = 0.f;

    #pragma unroll
    for (int it = 0; it < 2; it++) {
        int idx = tid + it * 256;
        int kf2 = idx >> 8, mb = (idx >> 6) & 3, ln = (idx >> 1) & 31, hf = idx & 1;
        cpa16(a_su[0] + (((kf2 * 4 + mb) * 32 + ln) * 8 + hf * 4) * 4,
              APK + ((size_t)((band0 + mb) * KFG + kf2) * 32 + ln) * 8 + hf * 4);
        int nf = (idx >> 5) & 7, lnb = idx & 31;
        cpa16(b_su[0] + ((kf2 * 8 + nf) * 32 + lnb) * 16,
              BPK + ((size_t)((nf0 + nf) * KFG + kf2) * 32 + lnb) * 4);
    }
    asm volatile("cp.async.commit_group;" ::: "memory");

    for (int ks = 0; ks < nslab; ks++) {
        const int cur = ks & 1;
        __syncthreads();
        if (ks + 1 < nslab) {
            const int st = cur ^ 1;
            #pragma unroll
            for (int it = 0; it < 2; it++) {
                int idx = tid + it * 256;
                int kf2 = idx >> 8, mb = (idx >> 6) & 3, ln = (idx >> 1) & 31, hf = idx & 1;
                int kfg = (ks + 1) * 2 + kf2;
                cpa16(a_su[st] + (((kf2 * 4 + mb) * 32 + ln) * 8 + hf * 4) * 4,
                      APK + ((size_t)((band0 + mb) * KFG + kfg) * 32 + ln) * 8 + hf * 4);
                int nf = (idx >> 5) & 7, lnb = idx & 31;
                cpa16(b_su[st] + ((kf2 * 8 + nf) * 32 + lnb) * 16,
                      BPK + ((size_t)((nf0 + nf) * KFG + kfg) * 32 + lnb) * 4);
            }
        }
        asm volatile("cp.async.commit_group;" ::: "memory");
        asm volatile("cp.async.wait_group 1;" ::: "memory");
        __syncthreads();

        uint32_t* AFc = AF + cur * 2048;
        uint32_t* BFc = BF + cur * 2048;
        #pragma unroll
        for (int kf2 = 0; kf2 < 2; kf2++) {
            const uint32_t* ap = &AFc[((kf2 * 4 + mw) * 32 + lane) * 8];
            uint4 ah = *(const uint4*)ap;
            uint4 al = *(const uint4*)(ap + 4);
            #pragma unroll
            for (int nf = 0; nf < 4; nf++) {
                uint4 kb = *(const uint4*)&BFc[((kf2 * 8 + nh * 4 + nf) * 32 + lane) * 4];
                mma16(cx.S[nf], ah.x, ah.y, ah.z, ah.w, kb.x, kb.y);
                mma16(cx.S[nf], al.x, al.y, al.z, al.w, kb.x, kb.y);
                mma16(cx.S[nf], ah.x, ah.y, ah.z, ah.w, kb.z, kb.w);
            }
        }
    }
    cx.colw = nh * 32;
}

// ---------------------------------------------------------------------------
// Fused Wq+Wkv GEMM: grid (10, 64). x<8 -> Wq (Q-norm -> g_q);
// x==8 -> K (norm -> g_kf frags, in-thread); x==9 -> V (-> g_vf, smem transpose).
// ---------------------------------------------------------------------------
__global__ __launch_bounds__(256) void gemm_qkv()
{
    __shared__ uint32_t AF[2 * 2048];
    __shared__ uint32_t BF[2 * 2048];
    __shared__ float ssbuf[128];
    __shared__ float vsm[64 * 68];

    const int tid = threadIdx.x, lane = tid & 31, w = tid >> 5;
    const int mw = w & 3, nh = w >> 2;
    const int gid = lane >> 2, tig = lane & 3;
    const int r0 = blockIdx.y * 64;
    const bool is_q = blockIdx.x < 8;
    const int xk = is_q ? blockIdx.x : blockIdx.x - 8;

    GemmCtx cx;
    gemm_core(g_xf, is_q ? g_wqf : g_wkvf, r0 >> 4, xk * 8, DIM >> 4, AF, BF, cx);

    const int bbr = r0 >> 11, ktr = (r0 & 2047) >> 6;
    const size_t obase = ((size_t)bbr * NT + ktr) * 1024;

    if (is_q || xk == 0) {
        #pragma unroll
        for (int rr = 0; rr < 2; rr++) {
            float ss = 0.f;
            #pragma unroll
            for (int nf = 0; nf < 4; nf++)
                ss += cx.S[nf][2 * rr] * cx.S[nf][2 * rr] + cx.S[nf][2 * rr + 1] * cx.S[nf][2 * rr + 1];
            ss += __shfl_xor_sync(0xffffffffu, ss, 1);
            ss += __shfl_xor_sync(0xffffffffu, ss, 2);
            if (tig == 0) ssbuf[nh * 64 + mw * 16 + gid + rr * 8] = ss;
        }
        __syncthreads();
        #pragma unroll
        for (int rr = 0; rr < 2; rr++) {
            int rloc = mw * 16 + gid + rr * 8;
            float ss = ssbuf[rloc] + ssbuf[64 + rloc];
            float inv = 1.0f / fmaxf(sqrtf(ss), 1e-12f);
            if (is_q) {
                int row = r0 + rloc;
                int bb = row >> 11, t = row & 2047;
                size_t base = (((size_t)bb * HEADS + blockIdx.x) * NSEQ + t) * DH;
                #pragma unroll
                for (int nf = 0; nf < 4; nf++) {
                    float2 v = make_float2(cx.S[nf][2 * rr] * inv, cx.S[nf][2 * rr + 1] * inv);
                    *(float2*)&g_q[base + cx.colw + nf * 8 + 2 * tig] = v;
                }
            } else {
                // K fragments: in-thread emission
                int nfp = mw * 2 + rr;
                #pragma unroll
                for (int p = 0; p < 2; p++) {
                    float a0 = cx.S[2 * p][2 * rr] * inv,     a1 = cx.S[2 * p][2 * rr + 1] * inv;
                    float c0 = cx.S[2 * p + 1][2 * rr] * inv, c1 = cx.S[2 * p + 1][2 * rr + 1] * inv;
                    uint32_t bl0, bl1;
                    uint32_t bh0 = split_pair_h(a0, a1, bl0);
                    uint32_t bh1 = split_pair_h(c0, c1, bl1);
                    int kfp = nh * 2 + p;
                    g_kf[obase + (nfp * 4 + kfp) * 32 + lane] = make_uint4(bh0, bh1, bl0, bl1);
                }
            }
        }
    } else {
        // V fragments: smem transpose then emit
        __syncthreads();
        #pragma unroll
        for (int rr = 0; rr < 2; rr++) {
            int rloc = mw * 16 + gid + rr * 8;
            #pragma unroll
            for (int nf = 0; nf < 4; nf++) {
                vsm[rloc * 68 + cx.colw + nf * 8 + 2 * tig]     = cx.S[nf][2 * rr];
                vsm[rloc * 68 + cx.colw + nf * 8 + 2 * tig + 1] = cx.S[nf][2 * rr + 1];
            }
        }
        __syncthreads();
        #pragma unroll
        for (int it = 0; it < 4; it++) {
            int s = tid + it * 256;
            int kg = s >> 8, nfd = (s >> 5) & 7, ln = s & 31;
            int gd = ln >> 2, tg = ln & 3;
            int key0 = kg * 16 + 2 * tg, d = nfd * 8 + gd;
            uint32_t b0 = h2bits(__floats2half2_rn(vsm[key0 * 68 + d], vsm[(key0 + 1) * 68 + d]));
            uint32_t b1 = h2bits(__floats2half2_rn(vsm[(key0 + 8) * 68 + d], vsm[(key0 + 9) * 68 + d]));
            g_vf[obase + s] = make_uint2(b0, b1);
        }
    }
}

// ---------------------------------------------------------------------------
__global__ __launch_bounds__(256) void gemm_out(float* __restrict__ C)
{
    __shared__ uint32_t AF[2 * 2048];
    __shared__ uint32_t BF[2 * 2048];

    const int tid = threadIdx.x, lane = tid & 31, w = tid >> 5;
    const int mw = w & 3;
    const int gid = lane >> 2, tig = lane & 3;
    const int r0 = blockIdx.y * 64, c0 = blockIdx.x * 64;

    GemmCtx cx;
    gemm_core(g_af, g_woutf, r0 >> 4, c0 >> 3, DIM >> 4, AF, BF, cx);
    const int row0 = r0 + mw * 16 + gid;

    #pragma unroll
    for (int rr = 0; rr < 2; rr++)
        #pragma unroll
        for (int nf = 0; nf < 4; nf++) {
            float2 v = make_float2(cx.S[nf][2 * rr], cx.S[nf][2 * rr + 1]);
            *(float2*)&C[(size_t)(row0 + rr * 8) * DIM + c0 + cx.colw + nf * 8 + 2 * tig] = v;
        }
}

// ---------------------------------------------------------------------------
// Flash attention (R10 structure, exp2-domain softmax).
// ---------------------------------------------------------------------------
#define STB 10752
__global__ __launch_bounds__(256, 2) void attn_mma(const float* __restrict__ memkv,
                                                   const float* __restrict__ rel,
                                                   const float* __restrict__ scale_param)
{
    extern __shared__ uint32_t smu[];
    uint32_t* QF  = smu;
    float* PMEM = (float*)(smu + 4096 + STB);
    float* OSM  = (float*)(smu + 4096 + STB + 2304);
    float* OMG  = (float*)(smu + 4096);
    float* RM   = (float*)(smu + 25600);
    float* RL   = RM + 128;

    const int bb = blockIdx.x, hh = blockIdx.y;
    const int qt = NT - 1 - (int)blockIdx.z;
    const int tid = threadIdx.x, lane = tid & 31, w = tid >> 5;
    const int mw = w & 3, ng = w >> 2;
    const int g = ng, gtid = tid & 127;
    const int gid = lane >> 2, tig = lane & 3;
    const int il0 = 16 * mw + gid;
    const float scaleL2 = expf(scale_param[hh]) * L2E;

    const uint32_t ks_su[2] = {s2u(smu + 4096  + g * 2048),
                               s2u(smu + 4096  + g * 2048 + STB)};
    const uint32_t vs_su[2] = {s2u(smu + 8192  + g * 1024),
                               s2u(smu + 8192  + g * 1024 + STB)};
    const uint32_t bs_su[2] = {s2u(smu + 10240 + g * 2304),
                               s2u(smu + 10240 + g * 2304 + STB)};
    const float* relrow = rel + ((size_t)hh * NSEQ + (size_t)qt * 64) * NSEQ;
    const uint4* ktileb = g_kf + (size_t)bb * NT * 1024 + g * 512;
    const uint4* vtileb = (const uint4*)(g_vf + (size_t)bb * NT * 1024 + g * 512);

    {
        #pragma unroll
        for (int it = 0; it < 4; it++)
            cpa16(ks_su[0] + (gtid + it * 128) * 16, ktileb + gtid + it * 128);
        #pragma unroll
        for (int it = 0; it < 2; it++)
            cpa16(vs_su[0] + (gtid + it * 128) * 16, vtileb + gtid + it * 128);
        const float* bsrc = relrow + g * 32;
        #pragma unroll
        for (int it = 0; it < 4; it++) {
            int c = gtid + it * 128;
            int r = c >> 3, c4 = c & 7;
            cpa16(bs_su[0] + (r * 36 + c4 * 4) * 4, bsrc + (size_t)r * NSEQ + c4 * 4);
        }
        asm volatile("cp.async.commit_group;" ::: "memory");
    }

    const float* qbase = g_q + (((size_t)bb * HEADS + hh) * NSEQ + (size_t)qt * 64) * DH;
    if (ng == 0) {
        #pragma unroll
        for (int kf = 0; kf < 4; kf++) {
            int d0 = kf * 16 + 2 * tig;
            float2 q00 = *(const float2*)&qbase[il0 * DH + d0];
            float2 q10 = *(const float2*)&qbase[(il0 + 8) * DH + d0];
            float2 q01 = *(const float2*)&qbase[il0 * DH + d0 + 8];
            float2 q11 = *(const float2*)&qbase[(il0 + 8) * DH + d0 + 8];
            uint32_t al0, al1, al2, al3;
            uint32_t ah0 = split_pair_h(q00.x, q00.y, al0);
            uint32_t ah1 = split_pair_h(q10.x, q10.y, al1);
            uint32_t ah2 = split_pair_h(q01.x, q01.y, al2);
            uint32_t ah3 = split_pair_h(q11.x, q11.y, al3);
            uint32_t* qp = &QF[((mw * 4 + kf) * 32 + lane) * 8];
            *(uint4*)qp       = make_uint4(ah0, ah1, ah2, ah3);
            *(uint4*)(qp + 4) = make_uint4(al0, al1, al2, al3);
        }
    }

    // ---- memory-attention prologue (SIMT fp32, log2-domain m) ----
    {
        int qi = tid >> 2, qtr = tid & 3;
        size_t gi = (size_t)qt * 64 + qi;
        const float* qrow = qbase + qi * DH + qtr * 16;
        float4 q4[4];
        #pragma unroll
        for (int u = 0; u < 4; u++) q4[u] = *(const float4*)&qrow[u * 4];
        const float* mk = memkv + ((((size_t)bb * HEADS + hh) * NSEQ + gi) * KRET) * 128
                        + qtr * 16;
        float sj[8];
        for (int j = 0; j < 32; j++) {
            const float* kp = mk + (size_t)j * 128;
            float p = 0.f;
            #pragma unroll
            for (int u = 0; u < 4; u++) {
                float4 k4 = *(const float4*)&kp[u * 4];
                p += q4[u].x * k4.x + q4[u].y * k4.y + q4[u].z * k4.z + q4[u].w * k4.w;
            }
            p += __shfl_xor_sync(0xffffffffu, p, 1);
            p += __shfl_xor_sync(0xffffffffu, p, 2);
            if ((j & 3) == qtr) sj[j >> 2] = p * scaleL2;
        }
        float mx = -3.0e38f;
        #pragma unroll
        for (int u = 0; u < 8; u++) mx = fmaxf(mx, sj[u]);
        mx = fmaxf(mx, __shfl_xor_sync(0xffffffffu, mx, 1));
        mx = fmaxf(mx, __shfl_xor_sync(0xffffffffu, mx, 2));
        float ls = 0.f;
        #pragma unroll
        for (int u = 0; u < 8; u++) {
            float pe = ex2(sj[u] - mx);
            ls += pe;
            PMEM[qi * 36 + u * 4 + qtr] = pe;
        }
        ls += __shfl_xor_sync(0xffffffffu, ls, 1);
        ls += __shfl_xor_sync(0xffffffffu, ls, 2);
        if (!qtr) { RM[qi] = mx; RL[qi] = ls; }
    }
    __syncthreads();

    {
        int qi = tid >> 2, qtr = tid & 3;
        size_t gi = (size_t)qt * 64 + qi;
        const float* vb = memkv + ((((size_t)bb * HEADS + hh) * NSEQ + gi) * KRET) * 128
                        + 64 + qtr * 16;
        float4 acc[4] = {};
        for (int j = 0; j < 32; j++) {
            float p = PMEM[qi * 36 + j];
            #pragma unroll
            for (int u = 0; u < 4; u++) {
                float4 v4 = *(const float4*)&vb[(size_t)j * 128 + u * 4];
                acc[u].x += p * v4.x; acc[u].y += p * v4.y;
                acc[u].z += p * v4.z; acc[u].w += p * v4.w;
            }
        }
        #pragma unroll
        for (int u = 0; u < 4; u++)
            *(float4*)&OSM[qi * 68 + qtr * 16 + u * 4] = acc[u];
    }
    __syncthreads();

    float O[8][4] = {}, m_r[2], l_r[2];
    if (ng == 0) {
        m_r[0] = RM[il0];     l_r[0] = RL[il0];
        m_r[1] = RM[il0 + 8]; l_r[1] = RL[il0 + 8];
        #pragma unroll
        for (int nf = 0; nf < 8; nf++) {
            O[nf][0] = OSM[il0 * 68 + nf * 8 + 2 * tig];
            O[nf][1] = OSM[il0 * 68 + nf * 8 + 2 * tig + 1];
            O[nf][2] = OSM[(il0 + 8) * 68 + nf * 8 + 2 * tig];
            O[nf][3] = OSM[(il0 + 8) * 68 + nf * 8 + 2 * tig + 1];
        }
    } else {
        m_r[0] = m_r[1] = -3.0e38f;
        l_r[0] = l_r[1] = 0.f;
    }
    __syncthreads();

    for (int kt = 0; kt <= qt; kt++) {
        const int cur = kt & 1;
        asm volatile("bar.sync %0, 128;" :: "r"(1 + g) : "memory");
        if (kt + 1 <= qt) {
            const int st = cur ^ 1;
            const uint4* ks = ktileb + (size_t)(kt + 1) * 1024;
            #pragma unroll
            for (int it = 0; it < 4; it++)
                cpa16(ks_su[st] + (gtid + it * 128) * 16, ks + gtid + it * 128);
            const uint4* vs = vtileb + (size_t)(kt + 1) * 512;
            #pragma unroll
            for (int it = 0; it < 2; it++)
                cpa16(vs_su[st] + (gtid + it * 128) * 16, vs + gtid + it * 128);
            const float* bsrc = relrow + (size_t)(kt + 1) * 64 + g * 32;
            #pragma unroll
            for (int it = 0; it < 4; it++) {
                int c = gtid + it * 128;
                int r = c >> 3, c4 = c & 7;
                cpa16(bs_su[st] + (r * 36 + c4 * 4) * 4, bsrc + (size_t)r * NSEQ + c4 * 4);
            }
        }
        asm volatile("cp.async.commit_group;" ::: "memory");
        asm volatile("cp.async.wait_group 1;" ::: "memory");
        asm volatile("bar.sync %0, 128;" :: "r"(1 + g) : "memory");

        const uint32_t* KSc = smu + 4096  + g * 2048 + cur * STB;
        const uint32_t* VSc = smu + 8192  + g * 1024 + cur * STB;
        const float*    BSc = (const float*)(smu + 10240 + g * 2304 + cur * STB);

        float S[4][4] = {};
        #pragma unroll
        for (int kf = 0; kf < 4; kf++) {
            const uint32_t* qp = &QF[((mw * 4 + kf) * 32 + lane) * 8];
            uint4 ah = *(const uint4*)qp;
            uint4 al = *(const uint4*)(qp + 4);
            #pragma unroll
            for (int nf = 0; nf < 4; nf++) {
                uint4 kb = *(const uint4*)&KSc[((nf * 4 + kf) * 32 + lane) * 4];
                mma16(S[nf], ah.x, ah.y, ah.z, ah.w, kb.x, kb.y);
                mma16(S[nf], al.x, al.y, al.z, al.w, kb.x, kb.y);
                mma16(S[nf], ah.x, ah.y, ah.z, ah.w, kb.z, kb.w);
            }
        }

        uint32_t ph[4][2];
        #pragma unroll
        for (int rr = 0; rr < 2; rr++) {
            int il = il0 + rr * 8;
            float mx = -3.0e38f;
            #pragma unroll
            for (int nf = 0; nf < 4; nf++) {
                int colb = g * 32 + nf * 8 + 2 * tig;
                float2 b2 = *(const float2*)&BSc[il * 36 + nf * 8 + 2 * tig];
                float s0 = fmaf(S[nf][2 * rr], scaleL2, b2.x * L2E);
                float s1 = fmaf(S[nf][2 * rr + 1], scaleL2, b2.y * L2E);
                if (kt == qt) {
                    if (colb     > il) s0 = -3.0e38f;
                    if (colb + 1 > il) s1 = -3.0e38f;
                }
                S[nf][2 * rr] = s0; S[nf][2 * rr + 1] = s1;
                mx = fmaxf(mx, fmaxf(s0, s1));
            }
            mx = fmaxf(mx, __shfl_xor_sync(0xffffffffu, mx, 1));
            mx = fmaxf(mx, __shfl_xor_sync(0xffffffffu, mx, 2));
            float mnew = fmaxf(m_r[rr], mx);
            float f = ex2(m_r[rr] - mnew);
            m_r[rr] = mnew;
            float ls = 0.f;
            #pragma unroll
            for (int nf = 0; nf < 4; nf++) {
                float p0 = ex2(S[nf][2 * rr] - mnew);
                float p1 = ex2(S[nf][2 * rr + 1] - mnew);
                ls += p0 + p1;
                ph[nf][rr] = h2bits(__floats2half2_rn(p0, p1));
            }
            #pragma unroll
            for (int nf = 0; nf < 8; nf++) {
                O[nf][2 * rr]     *= f;
                O[nf][2 * rr + 1] *= f;
            }
            ls += __shfl_xor_sync(0xffffffffu, ls, 1);
            ls += __shfl_xor_sync(0xffffffffu, ls, 2);
            l_r[rr] = l_r[rr] * f + ls;
        }

        #pragma unroll
        for (int kfl = 0; kfl < 2; kfl++) {
            uint32_t a0 = ph[2 * kfl][0], a1 = ph[2 * kfl][1];
            uint32_t a2 = ph[2 * kfl + 1][0], a3 = ph[2 * kfl + 1][1];
            #pragma unroll
            for (int nfd = 0; nfd < 8; nfd++) {
                uint2 vb = *(const uint2*)&VSc[((kfl * 8 + nfd) * 32 + lane) * 2];
                mma16(O[nfd], a0, a1, a2, a3, vb.x, vb.y);
            }
        }
    }

    asm volatile("cp.async.wait_group 0;" ::: "memory");
    __syncthreads();
    if (ng == 1) {
        #pragma unroll
        for (int rr = 0; rr < 2; rr++) {
            int il = il0 + rr * 8;
            RM[64 + il] = m_r[rr];
            RL[64 + il] = l_r[rr];
            #pragma unroll
            for (int nf = 0; nf < 8; nf++) {
                float2 v = make_float2(O[nf][2 * rr], O[nf][2 * rr + 1]);
                *(float2*)&OMG[il * 72 + nf * 8 + 2 * tig] = v;
            }
        }
    }
    __syncthreads();
    if (ng == 0) {
        #pragma unroll
        for (int rr = 0; rr < 2; rr++) {
            int il = il0 + rr * 8;
            float m1 = RM[64 + il], l1 = RL[64 + il];
            float m = fmaxf(m_r[rr], m1);
            float f0 = ex2(m_r[rr] - m), f1 = ex2(m1 - m);
            float inv = 1.0f / (l_r[rr] * f0 + l1 * f1);
            #pragma unroll
            for (int nf = 0; nf < 8; nf++) {
                float2 o1 = *(const float2*)&OMG[il * 72 + nf * 8 + 2 * tig];
                O[nf][2 * rr]     = (O[nf][2 * rr]     * f0 + o1.x * f1) * inv;
                O[nf][2 * rr + 1] = (O[nf][2 * rr + 1] * f0 + o1.y * f1) * inv;
            }
        }
        int band = bb * 128 + qt * 4 + mw;
        #pragma unroll
        for (int kf = 0; kf < 4; kf++) {
            uint32_t l0, l1, l2, l3;
            uint32_t h0 = split_pair_h(O[2 * kf][0],     O[2 * kf][1],     l0);
            uint32_t h1 = split_pair_h(O[2 * kf][2],     O[2 * kf][3],     l1);
            uint32_t h2 = split_pair_h(O[2 * kf + 1][0], O[2 * kf + 1][1], l2);
            uint32_t h3 = split_pair_h(O[2 * kf + 1][2], O[2 * kf + 1][3], l3);
            size_t slot = ((size_t)band * 32 + (hh * 4 + kf)) * 32 + lane;
            *(uint4*)&g_af[slot * 8]     = make_uint4(h0, h1, h2, h3);
            *(uint4*)&g_af[slot * 8 + 4] = make_uint4(l0, l1, l2, l3);
        }
    }
}

// ---------------------------------------------------------------------------
extern "C" void kernel_launch(void* const* d_in, const int* in_sizes, int n_in,
                              void* d_out, int out_size)
{
    const float* x      = (const float*)d_in[0];
    const float* memkv  = (const float*)d_in[1];
    const float* rel    = (const float*)d_in[3];
    const float* Wq     = (const float*)d_in[4];
    const float* Wkv    = (const float*)d_in[5];
    const float* Wout   = (const float*)d_in[6];
    const float* scalep = (const float*)d_in[7];
    float* out = (float*)d_out;

    const int SMEM = 25856 * (int)sizeof(uint32_t);   // 103424 B
    cudaFuncSetAttribute(attn_mma, cudaFuncAttributeMaxDynamicSharedMemorySize, SMEM);

    const int M = BATCH * NSEQ;
    pack_in<<<1792, 256>>>(x, Wq, Wkv, Wout);
    gemm_qkv<<<dim3(10, M / 64), 256>>>();
    attn_mma<<<dim3(BATCH, HEADS, NT), 256, SMEM>>>(memkv, rel, scalep);
    gemm_out<<<dim3(DIM / 64, M / 64), 256>>>(out);
}

// round 13
// speedup vs baseline: 1.1037x; 1.0231x over previous
#include <cuda_runtime.h>
#include <cuda_fp16.h>
#include <math.h>
#include <stdint.h>

#define NSEQ 2048
#define BATCH 2
#define HEADS 8
#define DH 64
#define KRET 32
#define DIM 512
#define NT 32
#define L2E 1.4426950408889634f

__device__ float g_q[(size_t)BATCH * HEADS * NSEQ * DH];
__device__ uint4 g_kf[(size_t)BATCH * NT * 1024];
__device__ uint2 g_vf[(size_t)BATCH * NT * 1024];
__device__ uint32_t g_xf[(size_t)256 * 32 * 32 * 8];
__device__ uint32_t g_af[(size_t)256 * 32 * 32 * 8];
__device__ uint32_t g_wqf[(size_t)64 * 32 * 32 * 4];
__device__ uint32_t g_wkvf[(size_t)16 * 32 * 32 * 4];
__device__ uint32_t g_woutf[(size_t)64 * 32 * 32 * 4];

__device__ __forceinline__ void mma16(float* d, uint32_t a0, uint32_t a1, uint32_t a2,
                                      uint32_t a3, uint32_t b0, uint32_t b1) {
    asm volatile("mma.sync.aligned.m16n8k16.row.col.f32.f16.f16.f32 "
        "{%0,%1,%2,%3}, {%4,%5,%6,%7}, {%8,%9}, {%0,%1,%2,%3};"
        : "+f"(d[0]), "+f"(d[1]), "+f"(d[2]), "+f"(d[3])
        : "r"(a0), "r"(a1), "r"(a2), "r"(a3), "r"(b0), "r"(b1));
}
__device__ __forceinline__ float ex2(float x) {
    float r; asm("ex2.approx.f32 %0, %1;" : "=f"(r) : "f"(x)); return r;
}
__device__ __forceinline__ uint32_t h2bits(__half2 h) {
    uint32_t u; *(__half2*)&u = h; return u;
}
__device__ __forceinline__ uint32_t split_pair_h(float a, float b, uint32_t& lo) {
    __half ha = __float2half_rn(a), hb = __float2half_rn(b);
    float ra = a - __half2float(ha), rb = b - __half2float(hb);
    lo = h2bits(__floats2half2_rn(ra, rb));
    return h2bits(__halves2half2(ha, hb));
}
__device__ __forceinline__ uint32_t s2u(const void* p) {
    return (uint32_t)__cvta_generic_to_shared(p);
}
__device__ __forceinline__ void cpa16(uint32_t s, const void* g) {
    asm volatile("cp.async.cg.shared.global [%0], [%1], 16;" :: "r"(s), "l"(g) : "memory");
}

// ---------------------------------------------------------------------------
// Merged input pack (unchanged from R12).
// ---------------------------------------------------------------------------
__global__ __launch_bounds__(256) void pack_in(const float* __restrict__ x,
                                               const float* __restrict__ Wq,
                                               const float* __restrict__ Wkv,
                                               const float* __restrict__ Wout)
{
    int bx = blockIdx.x;
    if (bx < 1024) {
        int s = bx * 256 + threadIdx.x;
        int band = s >> 10, rem = s & 1023;
        int kfg = rem >> 5, ln = rem & 31;
        int gid = ln >> 2, tig = ln & 3;
        const float* base = x + (size_t)(band * 16 + gid) * DIM + kfg * 16 + 2 * tig;
        float2 x00 = *(const float2*)base;
        float2 x10 = *(const float2*)(base + 8 * DIM);
        float2 x01 = *(const float2*)(base + 8);
        float2 x11 = *(const float2*)(base + 8 * DIM + 8);
        uint32_t l0, l1, l2, l3;
        uint32_t h0 = split_pair_h(x00.x, x00.y, l0);
        uint32_t h1 = split_pair_h(x10.x, x10.y, l1);
        uint32_t h2 = split_pair_h(x01.x, x01.y, l2);
        uint32_t h3 = split_pair_h(x11.x, x11.y, l3);
        *(uint4*)&g_xf[(size_t)s * 8]     = make_uint4(h0, h1, h2, h3);
        *(uint4*)&g_xf[(size_t)s * 8 + 4] = make_uint4(l0, l1, l2, l3);
    } else {
        int sel = (bx - 1024) >> 8;
        const float* W = sel == 0 ? Wq : (sel == 1 ? Wkv : Wout);
        uint32_t* out  = sel == 0 ? g_wqf : (sel == 1 ? g_wkvf : g_woutf);
        int N = (sel == 1) ? 128 : 512;
        int s = ((bx - 1024) & 255) * 256 + threadIdx.x;
        if (s >= (N / 8) * 1024) return;
        int nfg = s >> 10, rem = s & 1023;
        int kfg = rem >> 5, ln = rem & 31;
        int gid = ln >> 2, tig = ln & 3;
        int n = nfg * 8 + gid, k0 = kfg * 16 + 2 * tig;
        uint32_t bl0, bl1;
        uint32_t bh0 = split_pair_h(W[(size_t)k0 * N + n], W[(size_t)(k0 + 1) * N + n], bl0);
        uint32_t bh1 = split_pair_h(W[(size_t)(k0 + 8) * N + n], W[(size_t)(k0 + 9) * N + n], bl1);
        *(uint4*)&out[(size_t)s * 4] = make_uint4(bh0, bh1, bl0, bl1);
    }
}

// ---------------------------------------------------------------------------
// Templated GEMM mainloop: 64 x (NF*8) tile, 256 threads (4 mw x 2 nh),
// k-slab 32, double-buffered. Warp covers 16 rows x NF*4 cols (NF/2 frags).
// ---------------------------------------------------------------------------
template <int NF>
__device__ __forceinline__ void gemm_core_t(const uint32_t* __restrict__ APK,
                                            const uint32_t* __restrict__ BPK,
                                            int band0, int nf0, int KFG,
                                            uint32_t* AF, uint32_t* BF,
                                            float S[][4])
{
    const int tid = threadIdx.x, lane = tid & 31, w = tid >> 5;
    const int mw = w & 3, nh = w >> 2;
    const int nslab = KFG >> 1;
    const int BSTG = NF * 256;   // u32 per B stage
    const uint32_t a_su[2] = {s2u(AF), s2u(AF + 2048)};
    const uint32_t b_su[2] = {s2u(BF), s2u(BF + BSTG)};

    #pragma unroll
    for (int r = 0; r < NF / 2; r++)
        #pragma unroll
        for (int c = 0; c < 4; c++) S[r][c] = 0.f;

    // prefetch slab 0
    #pragma unroll
    for (int it = 0; it < 2; it++) {
        int idx = tid + it * 256;
        int kf2 = idx >> 8, mb = (idx >> 6) & 3, ln = (idx >> 1) & 31, hf = idx & 1;
        cpa16(a_su[0] + (((kf2 * 4 + mb) * 32 + ln) * 8 + hf * 4) * 4,
              APK + ((size_t)((band0 + mb) * KFG + kf2) * 32 + ln) * 8 + hf * 4);
    }
    #pragma unroll
    for (int it = 0; it < NF / 4; it++) {
        int idx = tid + it * 256;
        int kf2 = idx / (32 * NF), nf = (idx >> 5) % NF, lnb = idx & 31;
        cpa16(b_su[0] + ((kf2 * NF + nf) * 32 + lnb) * 16,
              BPK + ((size_t)((nf0 + nf) * KFG + kf2) * 32 + lnb) * 4);
    }
    asm volatile("cp.async.commit_group;" ::: "memory");

    for (int ks = 0; ks < nslab; ks++) {
        const int cur = ks & 1;
        __syncthreads();
        if (ks + 1 < nslab) {
            const int st = cur ^ 1;
            #pragma unroll
            for (int it = 0; it < 2; it++) {
                int idx = tid + it * 256;
                int kf2 = idx >> 8, mb = (idx >> 6) & 3, ln = (idx >> 1) & 31, hf = idx & 1;
                int kfg = (ks + 1) * 2 + kf2;
                cpa16(a_su[st] + (((kf2 * 4 + mb) * 32 + ln) * 8 + hf * 4) * 4,
                      APK + ((size_t)((band0 + mb) * KFG + kfg) * 32 + ln) * 8 + hf * 4);
            }
            #pragma unroll
            for (int it = 0; it < NF / 4; it++) {
                int idx = tid + it * 256;
                int kf2 = idx / (32 * NF), nf = (idx >> 5) % NF, lnb = idx & 31;
                int kfg = (ks + 1) * 2 + kf2;
                cpa16(b_su[st] + ((kf2 * NF + nf) * 32 + lnb) * 16,
                      BPK + ((size_t)((nf0 + nf) * KFG + kfg) * 32 + lnb) * 4);
            }
        }
        asm volatile("cp.async.commit_group;" ::: "memory");
        asm volatile("cp.async.wait_group 1;" ::: "memory");
        __syncthreads();

        uint32_t* AFc = AF + cur * 2048;
        uint32_t* BFc = BF + cur * BSTG;
        #pragma unroll
        for (int kf2 = 0; kf2 < 2; kf2++) {
            const uint32_t* ap = &AFc[((kf2 * 4 + mw) * 32 + lane) * 8];
            uint4 ah = *(const uint4*)ap;
            uint4 al = *(const uint4*)(ap + 4);
            #pragma unroll
            for (int nf = 0; nf < NF / 2; nf++) {
                uint4 kb = *(const uint4*)&BFc[((kf2 * NF + nh * (NF / 2) + nf) * 32 + lane) * 4];
                mma16(S[nf], ah.x, ah.y, ah.z, ah.w, kb.x, kb.y);
                mma16(S[nf], al.x, al.y, al.z, al.w, kb.x, kb.y);
                mma16(S[nf], ah.x, ah.y, ah.z, ah.w, kb.z, kb.w);
            }
        }
    }
}

// ---------------------------------------------------------------------------
// Fused QKV GEMM: grid (6, 64). bx<4 -> Wq 128-wide (warp = one head, warp-
// complete norm); bx==4 -> K (frags); bx==5 -> V (frags via transpose).
// ---------------------------------------------------------------------------
__global__ __launch_bounds__(256) void gemm_qkv()
{
    __shared__ uint32_t AF[2 * 2048];
    __shared__ uint32_t BF[2 * 4096];
    float* vsm   = (float*)BF;    // alias (used after mainloop drained)
    float* ssbuf = (float*)AF;    // alias

    const int tid = threadIdx.x, lane = tid & 31, w = tid >> 5;
    const int mw = w & 3, nh = w >> 2;
    const int gid = lane >> 2, tig = lane & 3;
    const int r0 = blockIdx.y * 64;
    const int bx = blockIdx.x;

    float S[8][4];

    if (bx < 4) {
        // ---- Wq: 64x128 tile, head = bx*2 + nh ----
        gemm_core_t<16>(g_xf, g_wqf, r0 >> 4, bx * 16, DIM >> 4, AF, BF, S);
        #pragma unroll
        for (int rr = 0; rr < 2; rr++) {
            float ss = 0.f;
            #pragma unroll
            for (int nf = 0; nf < 8; nf++)
                ss += S[nf][2 * rr] * S[nf][2 * rr] + S[nf][2 * rr + 1] * S[nf][2 * rr + 1];
            ss += __shfl_xor_sync(0xffffffffu, ss, 1);
            ss += __shfl_xor_sync(0xffffffffu, ss, 2);
            float inv = 1.0f / fmaxf(sqrtf(ss), 1e-12f);
            int row = r0 + mw * 16 + gid + rr * 8;
            int bb = row >> 11, t = row & 2047;
            size_t base = (((size_t)bb * HEADS + bx * 2 + nh) * NSEQ + t) * DH;
            #pragma unroll
            for (int nf = 0; nf < 8; nf++) {
                float2 v = make_float2(S[nf][2 * rr] * inv, S[nf][2 * rr + 1] * inv);
                *(float2*)&g_q[base + nf * 8 + 2 * tig] = v;
            }
        }
        return;
    }

    const bool is_k = (bx == 4);
    gemm_core_t<8>(g_xf, g_wkvf, r0 >> 4, is_k ? 0 : 8, DIM >> 4, AF, BF, S);
    const int colw = nh * 32;
    const int bbr = r0 >> 11, ktr = (r0 & 2047) >> 6;
    const size_t obase = ((size_t)bbr * NT + ktr) * 1024;

    if (is_k) {
        __syncthreads();  // AF stage reads done before ssbuf alias writes
        #pragma unroll
        for (int rr = 0; rr < 2; rr++) {
            float ss = 0.f;
            #pragma unroll
            for (int nf = 0; nf < 4; nf++)
                ss += S[nf][2 * rr] * S[nf][2 * rr] + S[nf][2 * rr + 1] * S[nf][2 * rr + 1];
            ss += __shfl_xor_sync(0xffffffffu, ss, 1);
            ss += __shfl_xor_sync(0xffffffffu, ss, 2);
            if (tig == 0) ssbuf[nh * 64 + mw * 16 + gid + rr * 8] = ss;
        }
        __syncthreads();
        #pragma unroll
        for (int rr = 0; rr < 2; rr++) {
            int rloc = mw * 16 + gid + rr * 8;
            float ss = ssbuf[rloc] + ssbuf[64 + rloc];
            float inv = 1.0f / fmaxf(sqrtf(ss), 1e-12f);
            int nfp = mw * 2 + rr;
            #pragma unroll
            for (int p = 0; p < 2; p++) {
                float a0 = S[2 * p][2 * rr] * inv,     a1 = S[2 * p][2 * rr + 1] * inv;
                float c0 = S[2 * p + 1][2 * rr] * inv, c1 = S[2 * p + 1][2 * rr + 1] * inv;
                uint32_t bl0, bl1;
                uint32_t bh0 = split_pair_h(a0, a1, bl0);
                uint32_t bh1 = split_pair_h(c0, c1, bl1);
                int kfp = nh * 2 + p;
                g_kf[obase + (nfp * 4 + kfp) * 32 + lane] = make_uint4(bh0, bh1, bl0, bl1);
            }
        }
    } else {
        __syncthreads();  // BF stage reads done before vsm alias writes
        #pragma unroll
        for (int rr = 0; rr < 2; rr++) {
            int rloc = mw * 16 + gid + rr * 8;
            #pragma unroll
            for (int nf = 0; nf < 4; nf++) {
                vsm[rloc * 68 + colw + nf * 8 + 2 * tig]     = S[nf][2 * rr];
                vsm[rloc * 68 + colw + nf * 8 + 2 * tig + 1] = S[nf][2 * rr + 1];
            }
        }
        __syncthreads();
        #pragma unroll
        for (int it = 0; it < 4; it++) {
            int s = tid + it * 256;
            int kg = s >> 8, nfd = (s >> 5) & 7, ln = s & 31;
            int gd = ln >> 2, tg = ln & 3;
            int key0 = kg * 16 + 2 * tg, d = nfd * 8 + gd;
            uint32_t b0 = h2bits(__floats2half2_rn(vsm[key0 * 68 + d], vsm[(key0 + 1) * 68 + d]));
            uint32_t b1 = h2bits(__floats2half2_rn(vsm[(key0 + 8) * 68 + d], vsm[(key0 + 9) * 68 + d]));
            g_vf[obase + s] = make_uint2(b0, b1);
        }
    }
}

// ---------------------------------------------------------------------------
// Output GEMM: 64x128 tiles, grid (4, 64) = 256 blocks = one wave.
// ---------------------------------------------------------------------------
__global__ __launch_bounds__(256) void gemm_out(float* __restrict__ C)
{
    __shared__ uint32_t AF[2 * 2048];
    __shared__ uint32_t BF[2 * 4096];

    const int tid = threadIdx.x, lane = tid & 31, w = tid >> 5;
    const int mw = w & 3, nh = w >> 2;
    const int gid = lane >> 2, tig = lane & 3;
    const int r0 = blockIdx.y * 64, c0 = blockIdx.x * 128;

    float S[8][4];
    gemm_core_t<16>(g_af, g_woutf, r0 >> 4, c0 >> 3, DIM >> 4, AF, BF, S);
    const int row0 = r0 + mw * 16 + gid;
    const int colw = nh * 64;

    #pragma unroll
    for (int rr = 0; rr < 2; rr++)
        #pragma unroll
        for (int nf = 0; nf < 8; nf++) {
            float2 v = make_float2(S[nf][2 * rr], S[nf][2 * rr + 1]);
            *(float2*)&C[(size_t)(row0 + rr * 8) * DIM + c0 + colw + nf * 8 + 2 * tig] = v;
        }
}

// ---------------------------------------------------------------------------
// Flash attention (unchanged from R12).
// ---------------------------------------------------------------------------
#define STB 10752
__global__ __launch_bounds__(256, 2) void attn_mma(const float* __restrict__ memkv,
                                                   const float* __restrict__ rel,
                                                   const float* __restrict__ scale_param)
{
    extern __shared__ uint32_t smu[];
    uint32_t* QF  = smu;
    float* PMEM = (float*)(smu + 4096 + STB);
    float* OSM  = (float*)(smu + 4096 + STB + 2304);
    float* OMG  = (float*)(smu + 4096);
    float* RM   = (float*)(smu + 25600);
    float* RL   = RM + 128;

    const int bb = blockIdx.x, hh = blockIdx.y;
    const int qt = NT - 1 - (int)blockIdx.z;
    const int tid = threadIdx.x, lane = tid & 31, w = tid >> 5;
    const int mw = w & 3, ng = w >> 2;
    const int g = ng, gtid = tid & 127;
    const int gid = lane >> 2, tig = lane & 3;
    const int il0 = 16 * mw + gid;
    const float scaleL2 = expf(scale_param[hh]) * L2E;

    const uint32_t ks_su[2] = {s2u(smu + 4096  + g * 2048),
                               s2u(smu + 4096  + g * 2048 + STB)};
    const uint32_t vs_su[2] = {s2u(smu + 8192  + g * 1024),
                               s2u(smu + 8192  + g * 1024 + STB)};
    const uint32_t bs_su[2] = {s2u(smu + 10240 + g * 2304),
                               s2u(smu + 10240 + g * 2304 + STB)};
    const float* relrow = rel + ((size_t)hh * NSEQ + (size_t)qt * 64) * NSEQ;
    const uint4* ktileb = g_kf + (size_t)bb * NT * 1024 + g * 512;
    const uint4* vtileb = (const uint4*)(g_vf + (size_t)bb * NT * 1024 + g * 512);

    {
        #pragma unroll
        for (int it = 0; it < 4; it++)
            cpa16(ks_su[0] + (gtid + it * 128) * 16, ktileb + gtid + it * 128);
        #pragma unroll
        for (int it = 0; it < 2; it++)
            cpa16(vs_su[0] + (gtid + it * 128) * 16, vtileb + gtid + it * 128);
        const float* bsrc = relrow + g * 32;
        #pragma unroll
        for (int it = 0; it < 4; it++) {
            int c = gtid + it * 128;
            int r = c >> 3, c4 = c & 7;
            cpa16(bs_su[0] + (r * 36 + c4 * 4) * 4, bsrc + (size_t)r * NSEQ + c4 * 4);
        }
        asm volatile("cp.async.commit_group;" ::: "memory");
    }

    const float* qbase = g_q + (((size_t)bb * HEADS + hh) * NSEQ + (size_t)qt * 64) * DH;
    if (ng == 0) {
        #pragma unroll
        for (int kf = 0; kf < 4; kf++) {
            int d0 = kf * 16 + 2 * tig;
            float2 q00 = *(const float2*)&qbase[il0 * DH + d0];
            float2 q10 = *(const float2*)&qbase[(il0 + 8) * DH + d0];
            float2 q01 = *(const float2*)&qbase[il0 * DH + d0 + 8];
            float2 q11 = *(const float2*)&qbase[(il0 + 8) * DH + d0 + 8];
            uint32_t al0, al1, al2, al3;
            uint32_t ah0 = split_pair_h(q00.x, q00.y, al0);
            uint32_t ah1 = split_pair_h(q10.x, q10.y, al1);
            uint32_t ah2 = split_pair_h(q01.x, q01.y, al2);
            uint32_t ah3 = split_pair_h(q11.x, q11.y, al3);
            uint32_t* qp = &QF[((mw * 4 + kf) * 32 + lane) * 8];
            *(uint4*)qp       = make_uint4(ah0, ah1, ah2, ah3);
            *(uint4*)(qp + 4) = make_uint4(al0, al1, al2, al3);
        }
    }

    {
        int qi = tid >> 2, qtr = tid & 3;
        size_t gi = (size_t)qt * 64 + qi;
        const float* qrow = qbase + qi * DH + qtr * 16;
        float4 q4[4];
        #pragma unroll
        for (int u = 0; u < 4; u++) q4[u] = *(const float4*)&qrow[u * 4];
        const float* mk = memkv + ((((size_t)bb * HEADS + hh) * NSEQ + gi) * KRET) * 128
                        + qtr * 16;
        float sj[8];
        for (int j = 0; j < 32; j++) {
            const float* kp = mk + (size_t)j * 128;
            float p = 0.f;
            #pragma unroll
            for (int u = 0; u < 4; u++) {
                float4 k4 = *(const float4*)&kp[u * 4];
                p += q4[u].x * k4.x + q4[u].y * k4.y + q4[u].z * k4.z + q4[u].w * k4.w;
            }
            p += __shfl_xor_sync(0xffffffffu, p, 1);
            p += __shfl_xor_sync(0xffffffffu, p, 2);
            if ((j & 3) == qtr) sj[j >> 2] = p * scaleL2;
        }
        float mx = -3.0e38f;
        #pragma unroll
        for (int u = 0; u < 8; u++) mx = fmaxf(mx, sj[u]);
        mx = fmaxf(mx, __shfl_xor_sync(0xffffffffu, mx, 1));
        mx = fmaxf(mx, __shfl_xor_sync(0xffffffffu, mx, 2));
        float ls = 0.f;
        #pragma unroll
        for (int u = 0; u < 8; u++) {
            float pe = ex2(sj[u] - mx);
            ls += pe;
            PMEM[qi * 36 + u * 4 + qtr] = pe;
        }
        ls += __shfl_xor_sync(0xffffffffu, ls, 1);
        ls += __shfl_xor_sync(0xffffffffu, ls, 2);
        if (!qtr) { RM[qi] = mx; RL[qi] = ls; }
    }
    __syncthreads();

    {
        int qi = tid >> 2, qtr = tid & 3;
        size_t gi = (size_t)qt * 64 + qi;
        const float* vb = memkv + ((((size_t)bb * HEADS + hh) * NSEQ + gi) * KRET) * 128
                        + 64 + qtr * 16;
        float4 acc[4] = {};
        for (int j = 0; j < 32; j++) {
            float p = PMEM[qi * 36 + j];
            #pragma unroll
            for (int u = 0; u < 4; u++) {
                float4 v4 = *(const float4*)&vb[(size_t)j * 128 + u * 4];
                acc[u].x += p * v4.x; acc[u].y += p * v4.y;
                acc[u].z += p * v4.z; acc[u].w += p * v4.w;
            }
        }
        #pragma unroll
        for (int u = 0; u < 4; u++)
            *(float4*)&OSM[qi * 68 + qtr * 16 + u * 4] = acc[u];
    }
    __syncthreads();

    float O[8][4] = {}, m_r[2], l_r[2];
    if (ng == 0) {
        m_r[0] = RM[il0];     l_r[0] = RL[il0];
        m_r[1] = RM[il0 + 8]; l_r[1] = RL[il0 + 8];
        #pragma unroll
        for (int nf = 0; nf < 8; nf++) {
            O[nf][0] = OSM[il0 * 68 + nf * 8 + 2 * tig];
            O[nf][1] = OSM[il0 * 68 + nf * 8 + 2 * tig + 1];
            O[nf][2] = OSM[(il0 + 8) * 68 + nf * 8 + 2 * tig];
            O[nf][3] = OSM[(il0 + 8) * 68 + nf * 8 + 2 * tig + 1];
        }
    } else {
        m_r[0] = m_r[1] = -3.0e38f;
        l_r[0] = l_r[1] = 0.f;
    }
    __syncthreads();

    for (int kt = 0; kt <= qt; kt++) {
        const int cur = kt & 1;
        asm volatile("bar.sync %0, 128;" :: "r"(1 + g) : "memory");
        if (kt + 1 <= qt) {
            const int st = cur ^ 1;
            const uint4* ks = ktileb + (size_t)(kt + 1) * 1024;
            #pragma unroll
            for (int it = 0; it < 4; it++)
                cpa16(ks_su[st] + (gtid + it * 128) * 16, ks + gtid + it * 128);
            const uint4* vs = vtileb + (size_t)(kt + 1) * 512;
            #pragma unroll
            for (int it = 0; it < 2; it++)
                cpa16(vs_su[st] + (gtid + it * 128) * 16, vs + gtid + it * 128);
            const float* bsrc = relrow + (size_t)(kt + 1) * 64 + g * 32;
            #pragma unroll
            for (int it = 0; it < 4; it++) {
                int c = gtid + it * 128;
                int r = c >> 3, c4 = c & 7;
                cpa16(bs_su[st] + (r * 36 + c4 * 4) * 4, bsrc + (size_t)r * NSEQ + c4 * 4);
            }
        }
        asm volatile("cp.async.commit_group;" ::: "memory");
        asm volatile("cp.async.wait_group 1;" ::: "memory");
        asm volatile("bar.sync %0, 128;" :: "r"(1 + g) : "memory");

        const uint32_t* KSc = smu + 4096  + g * 2048 + cur * STB;
        const uint32_t* VSc = smu + 8192  + g * 1024 + cur * STB;
        const float*    BSc = (const float*)(smu + 10240 + g * 2304 + cur * STB);

        float S[4][4] = {};
        #pragma unroll
        for (int kf = 0; kf < 4; kf++) {
            const uint32_t* qp = &QF[((mw * 4 + kf) * 32 + lane) * 8];
            uint4 ah = *(const uint4*)qp;
            uint4 al = *(const uint4*)(qp + 4);
            #pragma unroll
            for (int nf = 0; nf < 4; nf++) {
                uint4 kb = *(const uint4*)&KSc[((nf * 4 + kf) * 32 + lane) * 4];
                mma16(S[nf], ah.x, ah.y, ah.z, ah.w, kb.x, kb.y);
                mma16(S[nf], al.x, al.y, al.z, al.w, kb.x, kb.y);
                mma16(S[nf], ah.x, ah.y, ah.z, ah.w, kb.z, kb.w);
            }
        }

        uint32_t ph[4][2];
        #pragma unroll
        for (int rr = 0; rr < 2; rr++) {
            int il = il0 + rr * 8;
            float mx = -3.0e38f;
            #pragma unroll
            for (int nf = 0; nf < 4; nf++) {
                int colb = g * 32 + nf * 8 + 2 * tig;
                float2 b2 = *(const float2*)&BSc[il * 36 + nf * 8 + 2 * tig];
                float s0 = fmaf(S[nf][2 * rr], scaleL2, b2.x * L2E);
                float s1 = fmaf(S[nf][2 * rr + 1], scaleL2, b2.y * L2E);
                if (kt == qt) {
                    if (colb     > il) s0 = -3.0e38f;
                    if (colb + 1 > il) s1 = -3.0e38f;
                }
                S[nf][2 * rr] = s0; S[nf][2 * rr + 1] = s1;
                mx = fmaxf(mx, fmaxf(s0, s1));
            }
            mx = fmaxf(mx, __shfl_xor_sync(0xffffffffu, mx, 1));
            mx = fmaxf(mx, __shfl_xor_sync(0xffffffffu, mx, 2));
            float mnew = fmaxf(m_r[rr], mx);
            float f = ex2(m_r[rr] - mnew);
            m_r[rr] = mnew;
            float ls = 0.f;
            #pragma unroll
            for (int nf = 0; nf < 4; nf++) {
                float p0 = ex2(S[nf][2 * rr] - mnew);
                float p1 = ex2(S[nf][2 * rr + 1] - mnew);
                ls += p0 + p1;
                ph[nf][rr] = h2bits(__floats2half2_rn(p0, p1));
            }
            #pragma unroll
            for (int nf = 0; nf < 8; nf++) {
                O[nf][2 * rr]     *= f;
                O[nf][2 * rr + 1] *= f;
            }
            ls += __shfl_xor_sync(0xffffffffu, ls, 1);
            ls += __shfl_xor_sync(0xffffffffu, ls, 2);
            l_r[rr] = l_r[rr] * f + ls;
        }

        #pragma unroll
        for (int kfl = 0; kfl < 2; kfl++) {
            uint32_t a0 = ph[2 * kfl][0], a1 = ph[2 * kfl][1];
            uint32_t a2 = ph[2 * kfl + 1][0], a3 = ph[2 * kfl + 1][1];
            #pragma unroll
            for (int nfd = 0; nfd < 8; nfd++) {
                uint2 vb = *(const uint2*)&VSc[((kfl * 8 + nfd) * 32 + lane) * 2];
                mma16(O[nfd], a0, a1, a2, a3, vb.x, vb.y);
            }
        }
    }

    asm volatile("cp.async.wait_group 0;" ::: "memory");
    __syncthreads();
    if (ng == 1) {
        #pragma unroll
        for (int rr = 0; rr < 2; rr++) {
            int il = il0 + rr * 8;
            RM[64 + il] = m_r[rr];
            RL[64 + il] = l_r[rr];
            #pragma unroll
            for (int nf = 0; nf < 8; nf++) {
                float2 v = make_float2(O[nf][2 * rr], O[nf][2 * rr + 1]);
                *(float2*)&OMG[il * 72 + nf * 8 + 2 * tig] = v;
            }
        }
    }
    __syncthreads();
    if (ng == 0) {
        #pragma unroll
        for (int rr = 0; rr < 2; rr++) {
            int il = il0 + rr * 8;
            float m1 = RM[64 + il], l1 = RL[64 + il];
            float m = fmaxf(m_r[rr], m1);
            float f0 = ex2(m_r[rr] - m), f1 = ex2(m1 - m);
            float inv = 1.0f / (l_r[rr] * f0 + l1 * f1);
            #pragma unroll
            for (int nf = 0; nf < 8; nf++) {
                float2 o1 = *(const float2*)&OMG[il * 72 + nf * 8 + 2 * tig];
                O[nf][2 * rr]     = (O[nf][2 * rr]     * f0 + o1.x * f1) * inv;
                O[nf][2 * rr + 1] = (O[nf][2 * rr + 1] * f0 + o1.y * f1) * inv;
            }
        }
        int band = bb * 128 + qt * 4 + mw;
        #pragma unroll
        for (int kf = 0; kf < 4; kf++) {
            uint32_t l0, l1, l2, l3;
            uint32_t h0 = split_pair_h(O[2 * kf][0],     O[2 * kf][1],     l0);
            uint32_t h1 = split_pair_h(O[2 * kf][2],     O[2 * kf][3],     l1);
            uint32_t h2 = split_pair_h(O[2 * kf + 1][0], O[2 * kf + 1][1], l2);
            uint32_t h3 = split_pair_h(O[2 * kf + 1][2], O[2 * kf + 1][3], l3);
            size_t slot = ((size_t)band * 32 + (hh * 4 + kf)) * 32 + lane;
            *(uint4*)&g_af[slot * 8]     = make_uint4(h0, h1, h2, h3);
            *(uint4*)&g_af[slot * 8 + 4] = make_uint4(l0, l1, l2, l3);
        }
    }
}

// ---------------------------------------------------------------------------
extern "C" void kernel_launch(void* const* d_in, const int* in_sizes, int n_in,
                              void* d_out, int out_size)
{
    const float* x      = (const float*)d_in[0];
    const float* memkv  = (const float*)d_in[1];
    const float* rel    = (const float*)d_in[3];
    const float* Wq     = (const float*)d_in[4];
    const float* Wkv    = (const float*)d_in[5];
    const float* Wout   = (const float*)d_in[6];
    const float* scalep = (const float*)d_in[7];
    float* out = (float*)d_out;

    const int SMEM = 25856 * (int)sizeof(uint32_t);   // 103424 B
    cudaFuncSetAttribute(attn_mma, cudaFuncAttributeMaxDynamicSharedMemorySize, SMEM);

    const int M = BATCH * NSEQ;
    pack_in<<<1792, 256>>>(x, Wq, Wkv, Wout);
    gemm_qkv<<<dim3(6, M / 64), 256>>>();
    attn_mma<<<dim3(BATCH, HEADS, NT), 256, SMEM>>>(memkv, rel, scalep);
    gemm_out<<<dim3(4, M / 64), 256>>>(out);
}

// round 14
// speedup vs baseline: 1.3944x; 1.2635x over previous
#include <cuda_runtime.h>
#include <cuda_fp16.h>
#include <math.h>
#include <stdint.h>

#define NSEQ 2048
#define BATCH 2
#define HEADS 8
#define DH 64
#define KRET 32
#define DIM 512
#define NT 32
#define L2E 1.4426950408889634f

__device__ float g_q[(size_t)BATCH * HEADS * NSEQ * DH];
__device__ uint2 g_kf[(size_t)BATCH * NT * 1024];          // K frags: hi only
__device__ uint2 g_vf[(size_t)BATCH * NT * 1024];
__device__ uint32_t g_xf[(size_t)256 * 32 * 32 * 8];
__device__ uint32_t g_af[(size_t)256 * 32 * 32 * 8];
__device__ uint32_t g_wqf[(size_t)64 * 32 * 32 * 4];
__device__ uint32_t g_wkvf[(size_t)16 * 32 * 32 * 4];
__device__ uint32_t g_woutf[(size_t)64 * 32 * 32 * 2];     // Wout frags: hi only

__device__ __forceinline__ void mma16(float* d, uint32_t a0, uint32_t a1, uint32_t a2,
                                      uint32_t a3, uint32_t b0, uint32_t b1) {
    asm volatile("mma.sync.aligned.m16n8k16.row.col.f32.f16.f16.f32 "
        "{%0,%1,%2,%3}, {%4,%5,%6,%7}, {%8,%9}, {%0,%1,%2,%3};"
        : "+f"(d[0]), "+f"(d[1]), "+f"(d[2]), "+f"(d[3])
        : "r"(a0), "r"(a1), "r"(a2), "r"(a3), "r"(b0), "r"(b1));
}
__device__ __forceinline__ float ex2(float x) {
    float r; asm("ex2.approx.f32 %0, %1;" : "=f"(r) : "f"(x)); return r;
}
__device__ __forceinline__ uint32_t h2bits(__half2 h) {
    uint32_t u; *(__half2*)&u = h; return u;
}
__device__ __forceinline__ uint32_t split_pair_h(float a, float b, uint32_t& lo) {
    __half ha = __float2half_rn(a), hb = __float2half_rn(b);
    float ra = a - __half2float(ha), rb = b - __half2float(hb);
    lo = h2bits(__floats2half2_rn(ra, rb));
    return h2bits(__halves2half2(ha, hb));
}
__device__ __forceinline__ uint32_t s2u(const void* p) {
    return (uint32_t)__cvta_generic_to_shared(p);
}
__device__ __forceinline__ void cpa16(uint32_t s, const void* g) {
    asm volatile("cp.async.cg.shared.global [%0], [%1], 16;" :: "r"(s), "l"(g) : "memory");
}

// ---------------------------------------------------------------------------
// Merged input pack. Wout packed hi-only (uint2 per slot).
// ---------------------------------------------------------------------------
__global__ __launch_bounds__(256) void pack_in(const float* __restrict__ x,
                                               const float* __restrict__ Wq,
                                               const float* __restrict__ Wkv,
                                               const float* __restrict__ Wout)
{
    int bx = blockIdx.x;
    if (bx < 1024) {
        int s = bx * 256 + threadIdx.x;
        int band = s >> 10, rem = s & 1023;
        int kfg = rem >> 5, ln = rem & 31;
        int gid = ln >> 2, tig = ln & 3;
        const float* base = x + (size_t)(band * 16 + gid) * DIM + kfg * 16 + 2 * tig;
        float2 x00 = *(const float2*)base;
        float2 x10 = *(const float2*)(base + 8 * DIM);
        float2 x01 = *(const float2*)(base + 8);
        float2 x11 = *(const float2*)(base + 8 * DIM + 8);
        uint32_t l0, l1, l2, l3;
        uint32_t h0 = split_pair_h(x00.x, x00.y, l0);
        uint32_t h1 = split_pair_h(x10.x, x10.y, l1);
        uint32_t h2 = split_pair_h(x01.x, x01.y, l2);
        uint32_t h3 = split_pair_h(x11.x, x11.y, l3);
        *(uint4*)&g_xf[(size_t)s * 8]     = make_uint4(h0, h1, h2, h3);
        *(uint4*)&g_xf[(size_t)s * 8 + 4] = make_uint4(l0, l1, l2, l3);
    } else {
        int sel = (bx - 1024) >> 8;
        const float* W = sel == 0 ? Wq : (sel == 1 ? Wkv : Wout);
        int N = (sel == 1) ? 128 : 512;
        int s = ((bx - 1024) & 255) * 256 + threadIdx.x;
        if (s >= (N / 8) * 1024) return;
        int nfg = s >> 10, rem = s & 1023;
        int kfg = rem >> 5, ln = rem & 31;
        int gid = ln >> 2, tig = ln & 3;
        int n = nfg * 8 + gid, k0 = kfg * 16 + 2 * tig;
        uint32_t bl0, bl1;
        uint32_t bh0 = split_pair_h(W[(size_t)k0 * N + n], W[(size_t)(k0 + 1) * N + n], bl0);
        uint32_t bh1 = split_pair_h(W[(size_t)(k0 + 8) * N + n], W[(size_t)(k0 + 9) * N + n], bl1);
        if (sel == 2) {
            *(uint2*)&g_woutf[(size_t)s * 2] = make_uint2(bh0, bh1);
        } else {
            uint32_t* out = sel == 0 ? g_wqf : g_wkvf;
            *(uint4*)&out[(size_t)s * 4] = make_uint4(bh0, bh1, bl0, bl1);
        }
    }
}

// ---------------------------------------------------------------------------
// Templated GEMM mainloop: 64 x (NF*8) tile, 256 threads.
// SPLITB=1: B frags uint4 (hi+lo), 3-mma. SPLITB=0: B frags uint2 (hi), 2-mma.
// ---------------------------------------------------------------------------
template <int NF, int SPLITB>
__device__ __forceinline__ void gemm_core_t(const uint32_t* __restrict__ APK,
                                            const uint32_t* __restrict__ BPK,
                                            int band0, int nf0, int KFG,
                                            uint32_t* AF, uint32_t* BF,
                                            float S[][4])
{
    const int tid = threadIdx.x, lane = tid & 31, w = tid >> 5;
    const int mw = w & 3, nh = w >> 2;
    const int nslab = KFG >> 1;
    const int BSTG = NF * (SPLITB ? 256 : 128);
    const int BITER = SPLITB ? NF / 4 : NF / 8;
    const uint32_t a_su[2] = {s2u(AF), s2u(AF + 2048)};
    const uint32_t b_su[2] = {s2u(BF), s2u(BF + BSTG)};

    #pragma unroll
    for (int r = 0; r < NF / 2; r++)
        #pragma unroll
        for (int c = 0; c < 4; c++) S[r][c] = 0.f;

    #pragma unroll
    for (int it = 0; it < 2; it++) {
        int idx = tid + it * 256;
        int kf2 = idx >> 8, mb = (idx >> 6) & 3, ln = (idx >> 1) & 31, hf = idx & 1;
        cpa16(a_su[0] + (((kf2 * 4 + mb) * 32 + ln) * 8 + hf * 4) * 4,
              APK + ((size_t)((band0 + mb) * KFG + kf2) * 32 + ln) * 8 + hf * 4);
    }
    #pragma unroll
    for (int it = 0; it < BITER; it++) {
        int idx = tid + it * 256;
        if (SPLITB) {
            int kf2 = idx / (32 * NF), nf = (idx >> 5) % NF, lnb = idx & 31;
            cpa16(b_su[0] + ((kf2 * NF + nf) * 32 + lnb) * 16,
                  BPK + ((size_t)((nf0 + nf) * KFG + kf2) * 32 + lnb) * 4);
        } else {
            int kf2 = idx / (NF * 16), rem = idx % (NF * 16);
            int nf = rem >> 4, cq = rem & 15;
            cpa16(b_su[0] + ((kf2 * NF + nf) * 64 + cq * 4) * 4,
                  BPK + ((size_t)(nf0 + nf) * KFG + kf2) * 64 + cq * 4);
        }
    }
    asm volatile("cp.async.commit_group;" ::: "memory");

    for (int ks = 0; ks < nslab; ks++) {
        const int cur = ks & 1;
        __syncthreads();
        if (ks + 1 < nslab) {
            const int st = cur ^ 1;
            #pragma unroll
            for (int it = 0; it < 2; it++) {
                int idx = tid + it * 256;
                int kf2 = idx >> 8, mb = (idx >> 6) & 3, ln = (idx >> 1) & 31, hf = idx & 1;
                int kfg = (ks + 1) * 2 + kf2;
                cpa16(a_su[st] + (((kf2 * 4 + mb) * 32 + ln) * 8 + hf * 4) * 4,
                      APK + ((size_t)((band0 + mb) * KFG + kfg) * 32 + ln) * 8 + hf * 4);
            }
            #pragma unroll
            for (int it = 0; it < BITER; it++) {
                int idx = tid + it * 256;
                if (SPLITB) {
                    int kf2 = idx / (32 * NF), nf = (idx >> 5) % NF, lnb = idx & 31;
                    int kfg = (ks + 1) * 2 + kf2;
                    cpa16(b_su[st] + ((kf2 * NF + nf) * 32 + lnb) * 16,
                          BPK + ((size_t)((nf0 + nf) * KFG + kfg) * 32 + lnb) * 4);
                } else {
                    int kf2 = idx / (NF * 16), rem = idx % (NF * 16);
                    int nf = rem >> 4, cq = rem & 15;
                    int kfg = (ks + 1) * 2 + kf2;
                    cpa16(b_su[st] + ((kf2 * NF + nf) * 64 + cq * 4) * 4,
                          BPK + ((size_t)(nf0 + nf) * KFG + kfg) * 64 + cq * 4);
                }
            }
        }
        asm volatile("cp.async.commit_group;" ::: "memory");
        asm volatile("cp.async.wait_group 1;" ::: "memory");
        __syncthreads();

        uint32_t* AFc = AF + cur * 2048;
        uint32_t* BFc = BF + cur * BSTG;
        #pragma unroll
        for (int kf2 = 0; kf2 < 2; kf2++) {
            const uint32_t* ap = &AFc[((kf2 * 4 + mw) * 32 + lane) * 8];
            uint4 ah = *(const uint4*)ap;
            uint4 al = *(const uint4*)(ap + 4);
            #pragma unroll
            for (int nf = 0; nf < NF / 2; nf++) {
                if (SPLITB) {
                    uint4 kb = *(const uint4*)&BFc[((kf2 * NF + nh * (NF / 2) + nf) * 32 + lane) * 4];
                    mma16(S[nf], ah.x, ah.y, ah.z, ah.w, kb.x, kb.y);
                    mma16(S[nf], al.x, al.y, al.z, al.w, kb.x, kb.y);
                    mma16(S[nf], ah.x, ah.y, ah.z, ah.w, kb.z, kb.w);
                } else {
                    uint2 kb = *(const uint2*)&BFc[((kf2 * NF + nh * (NF / 2) + nf) * 32 + lane) * 2];
                    mma16(S[nf], ah.x, ah.y, ah.z, ah.w, kb.x, kb.y);
                    mma16(S[nf], al.x, al.y, al.z, al.w, kb.x, kb.y);
                }
            }
        }
    }
}

// ---------------------------------------------------------------------------
// Fused QKV GEMM: grid (6, 64). bx<4 -> Wq 128-wide; bx==4 -> K; bx==5 -> V.
// ---------------------------------------------------------------------------
__global__ __launch_bounds__(256) void gemm_qkv()
{
    __shared__ uint32_t AF[2 * 2048];
    __shared__ uint32_t BF[2 * 4096];
    float* vsm   = (float*)BF;
    float* ssbuf = (float*)AF;

    const int tid = threadIdx.x, lane = tid & 31, w = tid >> 5;
    const int mw = w & 3, nh = w >> 2;
    const int gid = lane >> 2, tig = lane & 3;
    const int r0 = blockIdx.y * 64;
    const int bx = blockIdx.x;

    float S[8][4];

    if (bx < 4) {
        gemm_core_t<16, 1>(g_xf, g_wqf, r0 >> 4, bx * 16, DIM >> 4, AF, BF, S);
        #pragma unroll
        for (int rr = 0; rr < 2; rr++) {
            float ss = 0.f;
            #pragma unroll
            for (int nf = 0; nf < 8; nf++)
                ss += S[nf][2 * rr] * S[nf][2 * rr] + S[nf][2 * rr + 1] * S[nf][2 * rr + 1];
            ss += __shfl_xor_sync(0xffffffffu, ss, 1);
            ss += __shfl_xor_sync(0xffffffffu, ss, 2);
            float inv = 1.0f / fmaxf(sqrtf(ss), 1e-12f);
            int row = r0 + mw * 16 + gid + rr * 8;
            int bb = row >> 11, t = row & 2047;
            size_t base = (((size_t)bb * HEADS + bx * 2 + nh) * NSEQ + t) * DH;
            #pragma unroll
            for (int nf = 0; nf < 8; nf++) {
                float2 v = make_float2(S[nf][2 * rr] * inv, S[nf][2 * rr + 1] * inv);
                *(float2*)&g_q[base + nf * 8 + 2 * tig] = v;
            }
        }
        return;
    }

    const bool is_k = (bx == 4);
    gemm_core_t<8, 1>(g_xf, g_wkvf, r0 >> 4, is_k ? 0 : 8, DIM >> 4, AF, BF, S);
    const int colw = nh * 32;
    const int bbr = r0 >> 11, ktr = (r0 & 2047) >> 6;
    const size_t obase = ((size_t)bbr * NT + ktr) * 1024;

    if (is_k) {
        __syncthreads();
        #pragma unroll
        for (int rr = 0; rr < 2; rr++) {
            float ss = 0.f;
            #pragma unroll
            for (int nf = 0; nf < 4; nf++)
                ss += S[nf][2 * rr] * S[nf][2 * rr] + S[nf][2 * rr + 1] * S[nf][2 * rr + 1];
            ss += __shfl_xor_sync(0xffffffffu, ss, 1);
            ss += __shfl_xor_sync(0xffffffffu, ss, 2);
            if (tig == 0) ssbuf[nh * 64 + mw * 16 + gid + rr * 8] = ss;
        }
        __syncthreads();
        #pragma unroll
        for (int rr = 0; rr < 2; rr++) {
            int rloc = mw * 16 + gid + rr * 8;
            float ss = ssbuf[rloc] + ssbuf[64 + rloc];
            float inv = 1.0f / fmaxf(sqrtf(ss), 1e-12f);
            int nfp = mw * 2 + rr;
            #pragma unroll
            for (int p = 0; p < 2; p++) {
                float a0 = S[2 * p][2 * rr] * inv,     a1 = S[2 * p][2 * rr + 1] * inv;
                float c0 = S[2 * p + 1][2 * rr] * inv, c1 = S[2 * p + 1][2 * rr + 1] * inv;
                uint32_t bh0 = h2bits(__floats2half2_rn(a0, a1));
                uint32_t bh1 = h2bits(__floats2half2_rn(c0, c1));
                int kfp = nh * 2 + p;
                g_kf[obase + (nfp * 4 + kfp) * 32 + lane] = make_uint2(bh0, bh1);
            }
        }
    } else {
        __syncthreads();
        #pragma unroll
        for (int rr = 0; rr < 2; rr++) {
            int rloc = mw * 16 + gid + rr * 8;
            #pragma unroll
            for (int nf = 0; nf < 4; nf++) {
                vsm[rloc * 68 + colw + nf * 8 + 2 * tig]     = S[nf][2 * rr];
                vsm[rloc * 68 + colw + nf * 8 + 2 * tig + 1] = S[nf][2 * rr + 1];
            }
        }
        __syncthreads();
        #pragma unroll
        for (int it = 0; it < 4; it++) {
            int s = tid + it * 256;
            int kg = s >> 8, nfd = (s >> 5) & 7, ln = s & 31;
            int gd = ln >> 2, tg = ln & 3;
            int key0 = kg * 16 + 2 * tg, d = nfd * 8 + gd;
            uint32_t b0 = h2bits(__floats2half2_rn(vsm[key0 * 68 + d], vsm[(key0 + 1) * 68 + d]));
            uint32_t b1 = h2bits(__floats2half2_rn(vsm[(key0 + 8) * 68 + d], vsm[(key0 + 9) * 68 + d]));
            g_vf[obase + s] = make_uint2(b0, b1);
        }
    }
}

// ---------------------------------------------------------------------------
// Output GEMM: 64x128 tiles, hi-only B (2-mma).
// ---------------------------------------------------------------------------
__global__ __launch_bounds__(256) void gemm_out(float* __restrict__ C)
{
    __shared__ uint32_t AF[2 * 2048];
    __shared__ uint32_t BF[2 * 2048];

    const int tid = threadIdx.x, lane = tid & 31, w = tid >> 5;
    const int mw = w & 3, nh = w >> 2;
    const int gid = lane >> 2, tig = lane & 3;
    const int r0 = blockIdx.y * 64, c0 = blockIdx.x * 128;

    float S[8][4];
    gemm_core_t<16, 0>(g_af, g_woutf, r0 >> 4, c0 >> 3, DIM >> 4, AF, BF, S);
    const int row0 = r0 + mw * 16 + gid;
    const int colw = nh * 64;

    #pragma unroll
    for (int rr = 0; rr < 2; rr++)
        #pragma unroll
        for (int nf = 0; nf < 8; nf++) {
            float2 v = make_float2(S[nf][2 * rr], S[nf][2 * rr + 1]);
            *(float2*)&C[(size_t)(row0 + rr * 8) * DIM + c0 + colw + nf * 8 + 2 * tig] = v;
        }
}

// ---------------------------------------------------------------------------
// Flash attention: K hi-only (2-mma QK). smem layout (u32):
// QF 0..4096 | stage0 4096..12800 | stage1 12800..21504 | RM/RL 21504..21760
// per stage: KS g0 1024, KS g1 1024, VS g0 1024, VS g1 1024, BS g0 2304, BS g1 2304
// ---------------------------------------------------------------------------
#define STB 8704
__global__ __launch_bounds__(256, 2) void attn_mma(const float* __restrict__ memkv,
                                                   const float* __restrict__ rel,
                                                   const float* __restrict__ scale_param)
{
    extern __shared__ uint32_t smu[];
    uint32_t* QF  = smu;
    float* PMEM = (float*)(smu + 4096 + STB);
    float* OSM  = (float*)(smu + 4096 + STB + 2304);
    float* OMG  = (float*)(smu + 4096);
    float* RM   = (float*)(smu + 4096 + 2 * STB);
    float* RL   = RM + 128;

    const int bb = blockIdx.x, hh = blockIdx.y;
    const int qt = NT - 1 - (int)blockIdx.z;
    const int tid = threadIdx.x, lane = tid & 31, w = tid >> 5;
    const int mw = w & 3, ng = w >> 2;
    const int g = ng, gtid = tid & 127;
    const int gid = lane >> 2, tig = lane & 3;
    const int il0 = 16 * mw + gid;
    const float scaleL2 = expf(scale_param[hh]) * L2E;

    const uint32_t ks_su[2] = {s2u(smu + 4096 + g * 1024),
                               s2u(smu + 4096 + g * 1024 + STB)};
    const uint32_t vs_su[2] = {s2u(smu + 6144 + g * 1024),
                               s2u(smu + 6144 + g * 1024 + STB)};
    const uint32_t bs_su[2] = {s2u(smu + 8192 + g * 2304),
                               s2u(smu + 8192 + g * 2304 + STB)};
    const float* relrow = rel + ((size_t)hh * NSEQ + (size_t)qt * 64) * NSEQ;
    const uint4* ktileb = (const uint4*)(g_kf + (size_t)bb * NT * 1024 + g * 512);
    const uint4* vtileb = (const uint4*)(g_vf + (size_t)bb * NT * 1024 + g * 512);

    {
        #pragma unroll
        for (int it = 0; it < 2; it++)
            cpa16(ks_su[0] + (gtid + it * 128) * 16, ktileb + gtid + it * 128);
        #pragma unroll
        for (int it = 0; it < 2; it++)
            cpa16(vs_su[0] + (gtid + it * 128) * 16, vtileb + gtid + it * 128);
        const float* bsrc = relrow + g * 32;
        #pragma unroll
        for (int it = 0; it < 4; it++) {
            int c = gtid + it * 128;
            int r = c >> 3, c4 = c & 7;
            cpa16(bs_su[0] + (r * 36 + c4 * 4) * 4, bsrc + (size_t)r * NSEQ + c4 * 4);
        }
        asm volatile("cp.async.commit_group;" ::: "memory");
    }

    const float* qbase = g_q + (((size_t)bb * HEADS + hh) * NSEQ + (size_t)qt * 64) * DH;
    if (ng == 0) {
        #pragma unroll
        for (int kf = 0; kf < 4; kf++) {
            int d0 = kf * 16 + 2 * tig;
            float2 q00 = *(const float2*)&qbase[il0 * DH + d0];
            float2 q10 = *(const float2*)&qbase[(il0 + 8) * DH + d0];
            float2 q01 = *(const float2*)&qbase[il0 * DH + d0 + 8];
            float2 q11 = *(const float2*)&qbase[(il0 + 8) * DH + d0 + 8];
            uint32_t al0, al1, al2, al3;
            uint32_t ah0 = split_pair_h(q00.x, q00.y, al0);
            uint32_t ah1 = split_pair_h(q10.x, q10.y, al1);
            uint32_t ah2 = split_pair_h(q01.x, q01.y, al2);
            uint32_t ah3 = split_pair_h(q11.x, q11.y, al3);
            uint32_t* qp = &QF[((mw * 4 + kf) * 32 + lane) * 8];
            *(uint4*)qp       = make_uint4(ah0, ah1, ah2, ah3);
            *(uint4*)(qp + 4) = make_uint4(al0, al1, al2, al3);
        }
    }

    // ---- memory-attention prologue (SIMT fp32) ----
    {
        int qi = tid >> 2, qtr = tid & 3;
        size_t gi = (size_t)qt * 64 + qi;
        const float* qrow = qbase + qi * DH + qtr * 16;
        float4 q4[4];
        #pragma unroll
        for (int u = 0; u < 4; u++) q4[u] = *(const float4*)&qrow[u * 4];
        const float* mk = memkv + ((((size_t)bb * HEADS + hh) * NSEQ + gi) * KRET) * 128
                        + qtr * 16;
        float sj[8];
        for (int j = 0; j < 32; j++) {
            const float* kp = mk + (size_t)j * 128;
            float p = 0.f;
            #pragma unroll
            for (int u = 0; u < 4; u++) {
                float4 k4 = *(const float4*)&kp[u * 4];
                p += q4[u].x * k4.x + q4[u].y * k4.y + q4[u].z * k4.z + q4[u].w * k4.w;
            }
            p += __shfl_xor_sync(0xffffffffu, p, 1);
            p += __shfl_xor_sync(0xffffffffu, p, 2);
            if ((j & 3) == qtr) sj[j >> 2] = p * scaleL2;
        }
        float mx = -3.0e38f;
        #pragma unroll
        for (int u = 0; u < 8; u++) mx = fmaxf(mx, sj[u]);
        mx = fmaxf(mx, __shfl_xor_sync(0xffffffffu, mx, 1));
        mx = fmaxf(mx, __shfl_xor_sync(0xffffffffu, mx, 2));
        float ls = 0.f;
        #pragma unroll
        for (int u = 0; u < 8; u++) {
            float pe = ex2(sj[u] - mx);
            ls += pe;
            PMEM[qi * 36 + u * 4 + qtr] = pe;
        }
        ls += __shfl_xor_sync(0xffffffffu, ls, 1);
        ls += __shfl_xor_sync(0xffffffffu, ls, 2);
        if (!qtr) { RM[qi] = mx; RL[qi] = ls; }
    }
    __syncthreads();

    {
        int qi = tid >> 2, qtr = tid & 3;
        size_t gi = (size_t)qt * 64 + qi;
        const float* vb = memkv + ((((size_t)bb * HEADS + hh) * NSEQ + gi) * KRET) * 128
                        + 64 + qtr * 16;
        float4 acc[4] = {};
        for (int j = 0; j < 32; j++) {
            float p = PMEM[qi * 36 + j];
            #pragma unroll
            for (int u = 0; u < 4; u++) {
                float4 v4 = *(const float4*)&vb[(size_t)j * 128 + u * 4];
                acc[u].x += p * v4.x; acc[u].y += p * v4.y;
                acc[u].z += p * v4.z; acc[u].w += p * v4.w;
            }
        }
        #pragma unroll
        for (int u = 0; u < 4; u++)
            *(float4*)&OSM[qi * 68 + qtr * 16 + u * 4] = acc[u];
    }
    __syncthreads();

    float O[8][4] = {}, m_r[2], l_r[2];
    if (ng == 0) {
        m_r[0] = RM[il0];     l_r[0] = RL[il0];
        m_r[1] = RM[il0 + 8]; l_r[1] = RL[il0 + 8];
        #pragma unroll
        for (int nf = 0; nf < 8; nf++) {
            O[nf][0] = OSM[il0 * 68 + nf * 8 + 2 * tig];
            O[nf][1] = OSM[il0 * 68 + nf * 8 + 2 * tig + 1];
            O[nf][2] = OSM[(il0 + 8) * 68 + nf * 8 + 2 * tig];
            O[nf][3] = OSM[(il0 + 8) * 68 + nf * 8 + 2 * tig + 1];
        }
    } else {
        m_r[0] = m_r[1] = -3.0e38f;
        l_r[0] = l_r[1] = 0.f;
    }
    __syncthreads();

    for (int kt = 0; kt <= qt; kt++) {
        const int cur = kt & 1;
        asm volatile("bar.sync %0, 128;" :: "r"(1 + g) : "memory");
        if (kt + 1 <= qt) {
            const int st = cur ^ 1;
            const uint4* ks = ktileb + (size_t)(kt + 1) * 256;
            #pragma unroll
            for (int it = 0; it < 2; it++)
                cpa16(ks_su[st] + (gtid + it * 128) * 16, ks + gtid + it * 128);
            const uint4* vs = vtileb + (size_t)(kt + 1) * 256;
            #pragma unroll
            for (int it = 0; it < 2; it++)
                cpa16(vs_su[st] + (gtid + it * 128) * 16, vs + gtid + it * 128);
            const float* bsrc = relrow + (size_t)(kt + 1) * 64 + g * 32;
            #pragma unroll
            for (int it = 0; it < 4; it++) {
                int c = gtid + it * 128;
                int r = c >> 3, c4 = c & 7;
                cpa16(bs_su[st] + (r * 36 + c4 * 4) * 4, bsrc + (size_t)r * NSEQ + c4 * 4);
            }
        }
        asm volatile("cp.async.commit_group;" ::: "memory");
        asm volatile("cp.async.wait_group 1;" ::: "memory");
        asm volatile("bar.sync %0, 128;" :: "r"(1 + g) : "memory");

        const uint32_t* KSc = smu + 4096 + g * 1024 + cur * STB;
        const uint32_t* VSc = smu + 6144 + g * 1024 + cur * STB;
        const float*    BSc = (const float*)(smu + 8192 + g * 2304 + cur * STB);

        // QK: Q split x K-hi (2-mma)
        float S[4][4] = {};
        #pragma unroll
        for (int kf = 0; kf < 4; kf++) {
            const uint32_t* qp = &QF[((mw * 4 + kf) * 32 + lane) * 8];
            uint4 ah = *(const uint4*)qp;
            uint4 al = *(const uint4*)(qp + 4);
            #pragma unroll
            for (int nf = 0; nf < 4; nf++) {
                uint2 kb = *(const uint2*)&KSc[((nf * 4 + kf) * 32 + lane) * 2];
                mma16(S[nf], ah.x, ah.y, ah.z, ah.w, kb.x, kb.y);
                mma16(S[nf], al.x, al.y, al.z, al.w, kb.x, kb.y);
            }
        }

        uint32_t ph[4][2];
        #pragma unroll
        for (int rr = 0; rr < 2; rr++) {
            int il = il0 + rr * 8;
            float mx = -3.0e38f;
            #pragma unroll
            for (int nf = 0; nf < 4; nf++) {
                int colb = g * 32 + nf * 8 + 2 * tig;
                float2 b2 = *(const float2*)&BSc[il * 36 + nf * 8 + 2 * tig];
                float s0 = fmaf(S[nf][2 * rr], scaleL2, b2.x * L2E);
                float s1 = fmaf(S[nf][2 * rr + 1], scaleL2, b2.y * L2E);
                if (kt == qt) {
                    if (colb     > il) s0 = -3.0e38f;
                    if (colb + 1 > il) s1 = -3.0e38f;
                }
                S[nf][2 * rr] = s0; S[nf][2 * rr + 1] = s1;
                mx = fmaxf(mx, fmaxf(s0, s1));
            }
            mx = fmaxf(mx, __shfl_xor_sync(0xffffffffu, mx, 1));
            mx = fmaxf(mx, __shfl_xor_sync(0xffffffffu, mx, 2));
            float mnew = fmaxf(m_r[rr], mx);
            float f = ex2(m_r[rr] - mnew);
            m_r[rr] = mnew;
            float ls = 0.f;
            #pragma unroll
            for (int nf = 0; nf < 4; nf++) {
                float p0 = ex2(S[nf][2 * rr] - mnew);
                float p1 = ex2(S[nf][2 * rr + 1] - mnew);
                ls += p0 + p1;
                ph[nf][rr] = h2bits(__floats2half2_rn(p0, p1));
            }
            #pragma unroll
            for (int nf = 0; nf < 8; nf++) {
                O[nf][2 * rr]     *= f;
                O[nf][2 * rr + 1] *= f;
            }
            ls += __shfl_xor_sync(0xffffffffu, ls, 1);
            ls += __shfl_xor_sync(0xffffffffu, ls, 2);
            l_r[rr] = l_r[rr] * f + ls;
        }

        #pragma unroll
        for (int kfl = 0; kfl < 2; kfl++) {
            uint32_t a0 = ph[2 * kfl][0], a1 = ph[2 * kfl][1];
            uint32_t a2 = ph[2 * kfl + 1][0], a3 = ph[2 * kfl + 1][1];
            #pragma unroll
            for (int nfd = 0; nfd < 8; nfd++) {
                uint2 vb = *(const uint2*)&VSc[((kfl * 8 + nfd) * 32 + lane) * 2];
                mma16(O[nfd], a0, a1, a2, a3, vb.x, vb.y);
            }
        }
    }

    asm volatile("cp.async.wait_group 0;" ::: "memory");
    __syncthreads();
    if (ng == 1) {
        #pragma unroll
        for (int rr = 0; rr < 2; rr++) {
            int il = il0 + rr * 8;
            RM[64 + il] = m_r[rr];
            RL[64 + il] = l_r[rr];
            #pragma unroll
            for (int nf = 0; nf < 8; nf++) {
                float2 v = make_float2(O[nf][2 * rr], O[nf][2 * rr + 1]);
                *(float2*)&OMG[il * 72 + nf * 8 + 2 * tig] = v;
            }
        }
    }
    __syncthreads();
    if (ng == 0) {
        #pragma unroll
        for (int rr = 0; rr < 2; rr++) {
            int il = il0 + rr * 8;
            float m1 = RM[64 + il], l1 = RL[64 + il];
            float m = fmaxf(m_r[rr], m1);
            float f0 = ex2(m_r[rr] - m), f1 = ex2(m1 - m);
            float inv = 1.0f / (l_r[rr] * f0 + l1 * f1);
            #pragma unroll
            for (int nf = 0; nf < 8; nf++) {
                float2 o1 = *(const float2*)&OMG[il * 72 + nf * 8 + 2 * tig];
                O[nf][2 * rr]     = (O[nf][2 * rr]     * f0 + o1.x * f1) * inv;
                O[nf][2 * rr + 1] = (O[nf][2 * rr + 1] * f0 + o1.y * f1) * inv;
            }
        }
        int band = bb * 128 + qt * 4 + mw;
        #pragma unroll
        for (int kf = 0; kf < 4; kf++) {
            uint32_t l0, l1, l2, l3;
            uint32_t h0 = split_pair_h(O[2 * kf][0],     O[2 * kf][1],     l0);
            uint32_t h1 = split_pair_h(O[2 * kf][2],     O[2 * kf][3],     l1);
            uint32_t h2 = split_pair_h(O[2 * kf + 1][0], O[2 * kf + 1][1], l2);
            uint32_t h3 = split_pair_h(O[2 * kf + 1][2], O[2 * kf + 1][3], l3);
            size_t slot = ((size_t)band * 32 + (hh * 4 + kf)) * 32 + lane;
            *(uint4*)&g_af[slot * 8]     = make_uint4(h0, h1, h2, h3);
            *(uint4*)&g_af[slot * 8 + 4] = make_uint4(l0, l1, l2, l3);
        }
    }
}

// ---------------------------------------------------------------------------
extern "C" void kernel_launch(void* const* d_in, const int* in_sizes, int n_in,
                              void* d_out, int out_size)
{
    const float* x      = (const float*)d_in[0];
    const float* memkv  = (const float*)d_in[1];
    const float* rel    = (const float*)d_in[3];
    const float* Wq     = (const float*)d_in[4];
    const float* Wkv    = (const float*)d_in[5];
    const float* Wout   = (const float*)d_in[6];
    const float* scalep = (const float*)d_in[7];
    float* out = (float*)d_out;

    const int SMEM = (4096 + 2 * STB + 256) * (int)sizeof(uint32_t);  // 87040 B
    cudaFuncSetAttribute(attn_mma, cudaFuncAttributeMaxDynamicSharedMemorySize, SMEM);

    const int M = BATCH * NSEQ;
    pack_in<<<1792, 256>>>(x, Wq, Wkv, Wout);
    gemm_qkv<<<dim3(6, M / 64), 256>>>();
    attn_mma<<<dim3(BATCH, HEADS, NT), 256, SMEM>>>(memkv, rel, scalep);
    gemm_out<<<dim3(4, M / 64), 256>>>(out);
}